// round 1
// baseline (speedup 1.0000x reference)
#include <cuda_runtime.h>
#include <cstdint>

// Problem constants (shapes fixed by the dataset)
#define NFEAT   256
#define NHID    128
#define NCLS    16
#define MAXN    100000
#define MAXE    1600000

// ---------------- scratch (device globals; no allocation allowed) ----------
__device__ int   g_cnt[MAXN];
__device__ int   g_cur[MAXN];
__device__ int   g_off[MAXN + 1];
__device__ float g_dinv[MAXN];
__device__ int   g_src[MAXE];
__device__ float g_w[MAXE];
__device__ float g_h1[(size_t)MAXN * NHID];
__device__ float g_g1[(size_t)MAXN * NHID];
__device__ float g_h2[(size_t)MAXN * NCLS];
__device__ int   g_is64;

// ---------------- index fetch (runtime int32/int64 dispatch) ---------------
__device__ __forceinline__ int edge_idx(const void* ei, long long pos, int is64) {
    if (is64) return (int)((const long long*)ei)[pos];
    return ((const int*)ei)[pos];
}

// ---------------- init: zero counters + detect index dtype -----------------
__global__ void k_init(const int* __restrict__ ei32, int n, int E) {
    int i = blockIdx.x * blockDim.x + threadIdx.x;
    if (i < n) g_cnt[i] = 0;
    if (blockIdx.x == 0) {
        // Check odd 32-bit words in the first min(4096, E/2) int64-candidates.
        // Safe under both layouts: 8192 int32s <= 2*E int32s always here.
        int samples = 4096;
        if (samples > E / 2) samples = E / 2;
        int nz = 0;
        for (int s = threadIdx.x; s < samples; s += blockDim.x)
            if (ei32[2 * s + 1] != 0) nz = 1;
        nz = __syncthreads_or(nz);
        if (threadIdx.x == 0) g_is64 = nz ? 0 : 1;
    }
}

// ---------------- degree count ---------------------------------------------
__global__ void k_count(const void* __restrict__ ei, int E) {
    int e = blockIdx.x * blockDim.x + threadIdx.x;
    if (e >= E) return;
    int c = edge_idx(ei, (long long)E + e, g_is64);
    atomicAdd(&g_cnt[c], 1);
}

__global__ void k_dinv(int n) {
    int i = blockIdx.x * blockDim.x + threadIdx.x;
    if (i < n) g_dinv[i] = rsqrtf((float)g_cnt[i] + 1.0f); // +1 = self loop
}

// ---------------- single-block exclusive scan of g_cnt -> g_off, g_cur -----
__global__ void k_scan(int n) {
    __shared__ int warp_sums[32];
    __shared__ int s_carry;
    int tid = threadIdx.x, lane = tid & 31, wid = tid >> 5;
    if (tid == 0) s_carry = 0;
    __syncthreads();
    for (int base = 0; base < n; base += 1024) {
        int i = base + tid;
        int v = (i < n) ? g_cnt[i] : 0;
        int x = v;
        #pragma unroll
        for (int d = 1; d < 32; d <<= 1) {
            int y = __shfl_up_sync(0xffffffffu, x, d);
            if (lane >= d) x += y;
        }
        if (lane == 31) warp_sums[wid] = x;
        __syncthreads();
        if (wid == 0) {
            int s = warp_sums[lane];
            #pragma unroll
            for (int d = 1; d < 32; d <<= 1) {
                int y = __shfl_up_sync(0xffffffffu, s, d);
                if (lane >= d) s += y;
            }
            warp_sums[lane] = s;
        }
        __syncthreads();
        int excl = x - v + (wid ? warp_sums[wid - 1] : 0) + s_carry;
        if (i < n) { g_off[i] = excl; g_cur[i] = excl; }
        int total = warp_sums[31];
        __syncthreads();
        if (tid == 0) s_carry += total;
        __syncthreads();
    }
    if (threadIdx.x == 0) g_off[n] = s_carry;
}

// ---------------- scatter edges into CSC -----------------------------------
__global__ void k_scatter(const void* __restrict__ ei, int E) {
    int e = blockIdx.x * blockDim.x + threadIdx.x;
    if (e >= E) return;
    int is64 = g_is64;
    int r = edge_idx(ei, e, is64);
    int c = edge_idx(ei, (long long)E + e, is64);
    int p = atomicAdd(&g_cur[c], 1);
    g_src[p] = r;
    g_w[p]   = g_dinv[r] * g_dinv[c];
}

// ---------------- GEMM1: h1 = x(Mx256) @ W1(256x128) -----------------------
__global__ void __launch_bounds__(256) k_gemm1(const float* __restrict__ A,
                                               const float* __restrict__ B,
                                               int M) {
    __shared__ float As[8][128]; // [k][row]
    __shared__ float Bs[8][128]; // [k][col]
    const int tid  = threadIdx.x;
    const int brow = blockIdx.x * 128;
    const int tx   = tid & 15;   // col group
    const int ty   = tid >> 4;   // row group

    float acc[8][8];
    #pragma unroll
    for (int i = 0; i < 8; i++)
        #pragma unroll
        for (int j = 0; j < 8; j++) acc[i][j] = 0.f;

    const int a_row = tid >> 1;          // 0..127
    const int a_k   = (tid & 1) * 4;     // 0 or 4
    const int b_k   = tid >> 5;          // 0..7
    const int b_col = (tid & 31) * 4;

    for (int k0 = 0; k0 < NFEAT; k0 += 8) {
        float4 av = make_float4(0.f, 0.f, 0.f, 0.f);
        int gr = brow + a_row;
        if (gr < M)
            av = *reinterpret_cast<const float4*>(&A[(long long)gr * NFEAT + k0 + a_k]);
        As[a_k + 0][a_row] = av.x;
        As[a_k + 1][a_row] = av.y;
        As[a_k + 2][a_row] = av.z;
        As[a_k + 3][a_row] = av.w;
        float4 bv = *reinterpret_cast<const float4*>(&B[(k0 + b_k) * NHID + b_col]);
        *reinterpret_cast<float4*>(&Bs[b_k][b_col]) = bv;
        __syncthreads();
        #pragma unroll
        for (int kk = 0; kk < 8; kk++) {
            float4 a0  = *reinterpret_cast<const float4*>(&As[kk][ty * 8]);
            float4 a1  = *reinterpret_cast<const float4*>(&As[kk][ty * 8 + 4]);
            float4 b0  = *reinterpret_cast<const float4*>(&Bs[kk][tx * 8]);
            float4 b1v = *reinterpret_cast<const float4*>(&Bs[kk][tx * 8 + 4]);
            float ar[8] = {a0.x, a0.y, a0.z, a0.w, a1.x, a1.y, a1.z, a1.w};
            float br[8] = {b0.x, b0.y, b0.z, b0.w, b1v.x, b1v.y, b1v.z, b1v.w};
            #pragma unroll
            for (int i = 0; i < 8; i++)
                #pragma unroll
                for (int j = 0; j < 8; j++)
                    acc[i][j] = fmaf(ar[i], br[j], acc[i][j]);
        }
        __syncthreads();
    }
    #pragma unroll
    for (int i = 0; i < 8; i++) {
        int gr = brow + ty * 8 + i;
        if (gr < M) {
            *reinterpret_cast<float4*>(&g_h1[(long long)gr * NHID + tx * 8]) =
                make_float4(acc[i][0], acc[i][1], acc[i][2], acc[i][3]);
            *reinterpret_cast<float4*>(&g_h1[(long long)gr * NHID + tx * 8 + 4]) =
                make_float4(acc[i][4], acc[i][5], acc[i][6], acc[i][7]);
        }
    }
}

// ---------------- agg1: g1 = relu(Ahat @ h1 + b1), warp per node -----------
__global__ void __launch_bounds__(256) k_agg1(const float* __restrict__ b1, int n) {
    int gtid = blockIdx.x * blockDim.x + threadIdx.x;
    int node = gtid >> 5;
    int lane = threadIdx.x & 31;
    if (node >= n) return;
    const float4* h1v = reinterpret_cast<const float4*>(g_h1);
    float dv = g_dinv[node];
    float sw = dv * dv;
    float4 hv = h1v[(long long)node * 32 + lane];
    float ax = hv.x * sw, ay = hv.y * sw, az = hv.z * sw, aw = hv.w * sw;

    int p = g_off[node], end = g_off[node + 1];
    for (; p + 1 < end; p += 2) {
        int   s0 = g_src[p],     s1 = g_src[p + 1];
        float w0 = g_w[p],       w1 = g_w[p + 1];
        float4 v0 = h1v[(long long)s0 * 32 + lane];
        float4 v1 = h1v[(long long)s1 * 32 + lane];
        ax += v0.x * w0 + v1.x * w1;
        ay += v0.y * w0 + v1.y * w1;
        az += v0.z * w0 + v1.z * w1;
        aw += v0.w * w0 + v1.w * w1;
    }
    if (p < end) {
        int s0 = g_src[p]; float w0 = g_w[p];
        float4 v0 = h1v[(long long)s0 * 32 + lane];
        ax += v0.x * w0; ay += v0.y * w0; az += v0.z * w0; aw += v0.w * w0;
    }
    float4 bb = reinterpret_cast<const float4*>(b1)[lane];
    float4 out;
    out.x = fmaxf(ax + bb.x, 0.f);
    out.y = fmaxf(ay + bb.y, 0.f);
    out.z = fmaxf(az + bb.z, 0.f);
    out.w = fmaxf(aw + bb.w, 0.f);
    reinterpret_cast<float4*>(g_g1)[(long long)node * 32 + lane] = out;
}

// ---------------- GEMM2: h2 = g1(Mx128) @ W2(128x16) -----------------------
__global__ void __launch_bounds__(256) k_gemm2(const float* __restrict__ W2, int M) {
    __shared__ float s_g[16 * 128];
    __shared__ float s_w[128 * 16];
    int node0 = blockIdx.x * 16;
    int tid = threadIdx.x;
    for (int idx = tid; idx < 2048; idx += 256) {
        s_w[idx] = W2[idx];
        int nd = idx >> 7;
        s_g[idx] = (node0 + nd < M) ? g_g1[(long long)node0 * 128 + idx] : 0.f;
    }
    __syncthreads();
    int nd = tid >> 4, j = tid & 15;
    float acc = 0.f;
    #pragma unroll
    for (int k = 0; k < 128; k++)
        acc = fmaf(s_g[nd * 128 + k], s_w[k * 16 + j], acc);
    if (node0 + nd < M)
        g_h2[(long long)(node0 + nd) * 16 + j] = acc;
}

// ---------------- agg2: out = Ahat @ h2 + b2, 16 threads per node ----------
__global__ void __launch_bounds__(256) k_agg2(const float* __restrict__ b2,
                                              float* __restrict__ out, int n) {
    int gtid = blockIdx.x * blockDim.x + threadIdx.x;
    int node = gtid >> 4;
    int lane = threadIdx.x & 15;
    if (node >= n) return;
    float dv = g_dinv[node];
    float acc = g_h2[(long long)node * 16 + lane] * dv * dv;
    int p = g_off[node], end = g_off[node + 1];
    for (; p + 1 < end; p += 2) {
        int   s0 = g_src[p], s1 = g_src[p + 1];
        float w0 = g_w[p],   w1 = g_w[p + 1];
        acc += g_h2[(long long)s0 * 16 + lane] * w0
             + g_h2[(long long)s1 * 16 + lane] * w1;
    }
    if (p < end)
        acc += g_h2[(long long)g_src[p] * 16 + lane] * g_w[p];
    out[(long long)node * 16 + lane] = acc + b2[lane];
}

// ---------------- launch ----------------------------------------------------
extern "C" void kernel_launch(void* const* d_in, const int* in_sizes, int n_in,
                              void* d_out, int out_size) {
    const float* x  = (const float*)d_in[0];
    const void*  ei = d_in[1];
    const float* W1 = (const float*)d_in[2];
    const float* b1 = (const float*)d_in[3];
    const float* W2 = (const float*)d_in[4];
    const float* b2 = (const float*)d_in[5];
    float* out = (float*)d_out;

    int n = in_sizes[0] / NFEAT;
    int E = in_sizes[1] / 2;

    int gN   = (n + 255) / 256;
    int gE   = (E + 255) / 256;

    k_init<<<gN, 256>>>((const int*)ei, n, E);
    k_count<<<gE, 256>>>(ei, E);
    k_dinv<<<gN, 256>>>(n);
    k_scan<<<1, 1024>>>(n);
    k_scatter<<<gE, 256>>>(ei, E);
    k_gemm1<<<(n + 127) / 128, 256>>>(x, W1, n);
    k_agg1<<<(n * 32 + 255) / 256, 256>>>(b1, n);
    k_gemm2<<<(n + 15) / 16, 256>>>(W2, n);
    k_agg2<<<(n * 16 + 255) / 256, 256>>>(b2, out, n);
}

// round 2
// speedup vs baseline: 1.1907x; 1.1907x over previous
#include <cuda_runtime.h>
#include <cstdint>

#define NFEAT   256
#define NHID    128
#define NCLS    16
#define MAXN    100000
#define MAXE    1600000
#define SCANB   1024
#define MAXBLK  128   // ceil(MAXN/SCANB) = 98

// ---------------- scratch (device globals; no allocation allowed) ----------
__device__ int   g_cnt[MAXN];
__device__ int   g_cur[MAXN];
__device__ int   g_off[MAXN + 1];
__device__ int   g_bsum[MAXBLK];
__device__ int   g_boff[MAXBLK];
__device__ float g_dinv[MAXN];
__device__ int   g_src[MAXE];
__device__ float g_w[MAXE];
__device__ float g_h1[(size_t)MAXN * NHID];
__device__ float g_g1[(size_t)MAXN * NHID];
__device__ float g_h2[(size_t)MAXN * NCLS];
__device__ int   g_is64;

// ---------------- index fetch (runtime int32/int64 dispatch) ---------------
__device__ __forceinline__ int edge_idx(const void* ei, long long pos, int is64) {
    if (is64) return (int)((const long long*)ei)[pos];
    return ((const int*)ei)[pos];
}

// ---------------- init: zero counters + detect index dtype -----------------
__global__ void k_init(const int* __restrict__ ei32, int n, int E) {
    int i = blockIdx.x * blockDim.x + threadIdx.x;
    if (i < n) g_cnt[i] = 0;
    if (blockIdx.x == 0) {
        int samples = 4096;
        if (samples > E / 2) samples = E / 2;
        int nz = 0;
        for (int s = threadIdx.x; s < samples; s += blockDim.x)
            if (ei32[2 * s + 1] != 0) nz = 1;
        nz = __syncthreads_or(nz);
        if (threadIdx.x == 0) g_is64 = nz ? 0 : 1;
    }
}

// ---------------- degree count ---------------------------------------------
__global__ void k_count(const void* __restrict__ ei, int E) {
    int e = blockIdx.x * blockDim.x + threadIdx.x;
    if (e >= E) return;
    int c = edge_idx(ei, (long long)E + e, g_is64);
    atomicAdd(&g_cnt[c], 1);
}

// ---------------- scan phase 1: per-block scan + dinv -----------------------
__global__ void __launch_bounds__(SCANB) k_scan_block(int n) {
    __shared__ int warp_sums[32];
    int tid = threadIdx.x, lane = tid & 31, wid = tid >> 5;
    int i = blockIdx.x * SCANB + tid;
    int v = (i < n) ? g_cnt[i] : 0;
    if (i < n) g_dinv[i] = rsqrtf((float)v + 1.0f); // +1 = self loop
    int x = v;
    #pragma unroll
    for (int d = 1; d < 32; d <<= 1) {
        int y = __shfl_up_sync(0xffffffffu, x, d);
        if (lane >= d) x += y;
    }
    if (lane == 31) warp_sums[wid] = x;
    __syncthreads();
    if (wid == 0) {
        int s = warp_sums[lane];
        #pragma unroll
        for (int d = 1; d < 32; d <<= 1) {
            int y = __shfl_up_sync(0xffffffffu, s, d);
            if (lane >= d) s += y;
        }
        warp_sums[lane] = s;
    }
    __syncthreads();
    int excl = x - v + (wid ? warp_sums[wid - 1] : 0);
    if (i < n) g_off[i] = excl;
    if (tid == SCANB - 1) g_bsum[blockIdx.x] = excl + v;
}

// ---------------- scan phase 2: scan of block sums (1 tiny block) ----------
__global__ void k_scan_tops(int nb, int n) {
    __shared__ int warp_sums[32];
    int tid = threadIdx.x, lane = tid & 31, wid = tid >> 5;
    int v = (tid < nb) ? g_bsum[tid] : 0;
    int x = v;
    #pragma unroll
    for (int d = 1; d < 32; d <<= 1) {
        int y = __shfl_up_sync(0xffffffffu, x, d);
        if (lane >= d) x += y;
    }
    if (lane == 31) warp_sums[wid] = x;
    __syncthreads();
    if (wid == 0) {
        int s = warp_sums[lane];
        #pragma unroll
        for (int d = 1; d < 32; d <<= 1) {
            int y = __shfl_up_sync(0xffffffffu, s, d);
            if (lane >= d) s += y;
        }
        warp_sums[lane] = s;
    }
    __syncthreads();
    int excl = x - v + (wid ? warp_sums[wid - 1] : 0);
    if (tid < nb) g_boff[tid] = excl;
    if (tid == nb - 1) g_off[n] = excl + v;
}

// ---------------- scan phase 3: add block offsets ---------------------------
__global__ void __launch_bounds__(SCANB) k_scan_add(int n) {
    int i = blockIdx.x * SCANB + threadIdx.x;
    if (i < n) {
        int v = g_off[i] + g_boff[blockIdx.x];
        g_off[i] = v;
        g_cur[i] = v;
    }
}

// ---------------- scatter edges into CSC -----------------------------------
__global__ void k_scatter(const void* __restrict__ ei, int E) {
    int e = blockIdx.x * blockDim.x + threadIdx.x;
    if (e >= E) return;
    int is64 = g_is64;
    int r = edge_idx(ei, e, is64);
    int c = edge_idx(ei, (long long)E + e, is64);
    int p = atomicAdd(&g_cur[c], 1);
    g_src[p] = r;
    g_w[p]   = g_dinv[r] * g_dinv[c];
}

// ---------------- GEMM1: h1 = x(Mx256) @ W1(256x128), KT=16 ----------------
__global__ void __launch_bounds__(256) k_gemm1(const float* __restrict__ A,
                                               const float* __restrict__ B,
                                               int M) {
    __shared__ float As[16][128]; // [k][row]
    __shared__ float Bs[16][128]; // [k][col]
    const int tid  = threadIdx.x;
    const int brow = blockIdx.x * 128;
    const int tx   = tid & 15;   // col group
    const int ty   = tid >> 4;   // row group

    float acc[8][8];
    #pragma unroll
    for (int i = 0; i < 8; i++)
        #pragma unroll
        for (int j = 0; j < 8; j++) acc[i][j] = 0.f;

    const int a_row = tid >> 1;          // 0..127
    const int a_k   = (tid & 1) * 8;     // 0 or 8
    const int b_k   = tid >> 5;          // 0..7
    const int b_col = (tid & 31) * 4;

    for (int k0 = 0; k0 < NFEAT; k0 += 16) {
        int gr = brow + a_row;
        float4 av0 = make_float4(0.f, 0.f, 0.f, 0.f);
        float4 av1 = make_float4(0.f, 0.f, 0.f, 0.f);
        if (gr < M) {
            av0 = *reinterpret_cast<const float4*>(&A[(long long)gr * NFEAT + k0 + a_k]);
            av1 = *reinterpret_cast<const float4*>(&A[(long long)gr * NFEAT + k0 + a_k + 4]);
        }
        As[a_k + 0][a_row] = av0.x;
        As[a_k + 1][a_row] = av0.y;
        As[a_k + 2][a_row] = av0.z;
        As[a_k + 3][a_row] = av0.w;
        As[a_k + 4][a_row] = av1.x;
        As[a_k + 5][a_row] = av1.y;
        As[a_k + 6][a_row] = av1.z;
        As[a_k + 7][a_row] = av1.w;
        float4 bv0 = *reinterpret_cast<const float4*>(&B[(k0 + b_k) * NHID + b_col]);
        float4 bv1 = *reinterpret_cast<const float4*>(&B[(k0 + b_k + 8) * NHID + b_col]);
        *reinterpret_cast<float4*>(&Bs[b_k][b_col])     = bv0;
        *reinterpret_cast<float4*>(&Bs[b_k + 8][b_col]) = bv1;
        __syncthreads();
        #pragma unroll
        for (int kk = 0; kk < 16; kk++) {
            float4 a0  = *reinterpret_cast<const float4*>(&As[kk][ty * 8]);
            float4 a1  = *reinterpret_cast<const float4*>(&As[kk][ty * 8 + 4]);
            float4 b0  = *reinterpret_cast<const float4*>(&Bs[kk][tx * 8]);
            float4 b1v = *reinterpret_cast<const float4*>(&Bs[kk][tx * 8 + 4]);
            float ar[8] = {a0.x, a0.y, a0.z, a0.w, a1.x, a1.y, a1.z, a1.w};
            float br[8] = {b0.x, b0.y, b0.z, b0.w, b1v.x, b1v.y, b1v.z, b1v.w};
            #pragma unroll
            for (int i = 0; i < 8; i++)
                #pragma unroll
                for (int j = 0; j < 8; j++)
                    acc[i][j] = fmaf(ar[i], br[j], acc[i][j]);
        }
        __syncthreads();
    }
    #pragma unroll
    for (int i = 0; i < 8; i++) {
        int gr = brow + ty * 8 + i;
        if (gr < M) {
            *reinterpret_cast<float4*>(&g_h1[(long long)gr * NHID + tx * 8]) =
                make_float4(acc[i][0], acc[i][1], acc[i][2], acc[i][3]);
            *reinterpret_cast<float4*>(&g_h1[(long long)gr * NHID + tx * 8 + 4]) =
                make_float4(acc[i][4], acc[i][5], acc[i][6], acc[i][7]);
        }
    }
}

// ---------------- agg1: g1 = relu(Ahat @ h1 + b1), warp per node -----------
__global__ void __launch_bounds__(256) k_agg1(const float* __restrict__ b1, int n) {
    int gtid = blockIdx.x * blockDim.x + threadIdx.x;
    int node = gtid >> 5;
    int lane = threadIdx.x & 31;
    if (node >= n) return;
    const float4* h1v = reinterpret_cast<const float4*>(g_h1);
    float dv = g_dinv[node];
    float sw = dv * dv;
    float4 hv = h1v[(long long)node * 32 + lane];
    float ax = hv.x * sw, ay = hv.y * sw, az = hv.z * sw, aw = hv.w * sw;

    int p = g_off[node], end = g_off[node + 1];
    for (; p + 1 < end; p += 2) {
        int   s0 = g_src[p],     s1 = g_src[p + 1];
        float w0 = g_w[p],       w1 = g_w[p + 1];
        float4 v0 = h1v[(long long)s0 * 32 + lane];
        float4 v1 = h1v[(long long)s1 * 32 + lane];
        ax += v0.x * w0 + v1.x * w1;
        ay += v0.y * w0 + v1.y * w1;
        az += v0.z * w0 + v1.z * w1;
        aw += v0.w * w0 + v1.w * w1;
    }
    if (p < end) {
        int s0 = g_src[p]; float w0 = g_w[p];
        float4 v0 = h1v[(long long)s0 * 32 + lane];
        ax += v0.x * w0; ay += v0.y * w0; az += v0.z * w0; aw += v0.w * w0;
    }
    float4 bb = reinterpret_cast<const float4*>(b1)[lane];
    float4 out;
    out.x = fmaxf(ax + bb.x, 0.f);
    out.y = fmaxf(ay + bb.y, 0.f);
    out.z = fmaxf(az + bb.z, 0.f);
    out.w = fmaxf(aw + bb.w, 0.f);
    reinterpret_cast<float4*>(g_g1)[(long long)node * 32 + lane] = out;
}

// ---------------- GEMM2: h2 = g1(Mx128) @ W2(128x16) -----------------------
__global__ void __launch_bounds__(256) k_gemm2(const float* __restrict__ W2, int M) {
    __shared__ float s_g[16 * 128];
    __shared__ float s_w[128 * 16];
    int node0 = blockIdx.x * 16;
    int tid = threadIdx.x;
    for (int idx = tid; idx < 2048; idx += 256) {
        s_w[idx] = W2[idx];
        int nd = idx >> 7;
        s_g[idx] = (node0 + nd < M) ? g_g1[(long long)node0 * 128 + idx] : 0.f;
    }
    __syncthreads();
    int nd = tid >> 4, j = tid & 15;
    float acc = 0.f;
    #pragma unroll
    for (int k = 0; k < 128; k++)
        acc = fmaf(s_g[nd * 128 + k], s_w[k * 16 + j], acc);
    if (node0 + nd < M)
        g_h2[(long long)(node0 + nd) * 16 + j] = acc;
}

// ---------------- agg2: out = Ahat @ h2 + b2, 16 threads per node ----------
__global__ void __launch_bounds__(256) k_agg2(const float* __restrict__ b2,
                                              float* __restrict__ out, int n) {
    int gtid = blockIdx.x * blockDim.x + threadIdx.x;
    int node = gtid >> 4;
    int lane = threadIdx.x & 15;
    if (node >= n) return;
    float dv = g_dinv[node];
    float acc = g_h2[(long long)node * 16 + lane] * dv * dv;
    int p = g_off[node], end = g_off[node + 1];
    for (; p + 1 < end; p += 2) {
        int   s0 = g_src[p], s1 = g_src[p + 1];
        float w0 = g_w[p],   w1 = g_w[p + 1];
        acc += g_h2[(long long)s0 * 16 + lane] * w0
             + g_h2[(long long)s1 * 16 + lane] * w1;
    }
    if (p < end)
        acc += g_h2[(long long)g_src[p] * 16 + lane] * g_w[p];
    out[(long long)node * 16 + lane] = acc + b2[lane];
}

// ---------------- launch ----------------------------------------------------
extern "C" void kernel_launch(void* const* d_in, const int* in_sizes, int n_in,
                              void* d_out, int out_size) {
    const float* x  = (const float*)d_in[0];
    const void*  ei = d_in[1];
    const float* W1 = (const float*)d_in[2];
    const float* b1 = (const float*)d_in[3];
    const float* W2 = (const float*)d_in[4];
    const float* b2 = (const float*)d_in[5];
    float* out = (float*)d_out;

    int n = in_sizes[0] / NFEAT;
    int E = in_sizes[1] / 2;

    int gN = (n + 255) / 256;
    int gE = (E + 255) / 256;
    int nb = (n + SCANB - 1) / SCANB;

    k_init<<<gN, 256>>>((const int*)ei, n, E);
    k_count<<<gE, 256>>>(ei, E);
    k_scan_block<<<nb, SCANB>>>(n);
    k_scan_tops<<<1, 128>>>(nb, n);
    k_scan_add<<<nb, SCANB>>>(n);
    k_scatter<<<gE, 256>>>(ei, E);
    k_gemm1<<<(n + 127) / 128, 256>>>(x, W1, n);
    k_agg1<<<(n * 32 + 255) / 256, 256>>>(b1, n);
    k_gemm2<<<(n + 15) / 16, 256>>>(W2, n);
    k_agg2<<<(n * 16 + 255) / 256, 256>>>(b2, out, n);
}

// round 4
// speedup vs baseline: 1.1973x; 1.0055x over previous
#include <cuda_runtime.h>
#include <cstdint>

#define NFEAT   256
#define NHID    128
#define NCLS    16
#define MAXN    100000
#define MAXE    1600000
#define SCANB   1024
#define MAXBLK  128

// ---------------- scratch (device globals; no allocation allowed) ----------
__device__ int   g_cnt[MAXN];
__device__ int   g_cur[MAXN];
__device__ int   g_off[MAXN + 1];
__device__ int   g_bsum[MAXBLK];
__device__ int   g_boff[MAXBLK];
__device__ float g_dinv[MAXN];
__device__ int   g_src[MAXE];
__device__ float g_w[MAXE];
__device__ float g_h1[(size_t)MAXN * NHID];
__device__ float g_g1[(size_t)MAXN * NHID];
__device__ float g_h2[(size_t)MAXN * NCLS];
__device__ int   g_is64;

// ---------------- index fetch (runtime int32/int64 dispatch) ---------------
__device__ __forceinline__ int edge_idx(const void* ei, long long pos, int is64) {
    if (is64) return (int)((const long long*)ei)[pos];
    return ((const int*)ei)[pos];
}

// ---------------- init: zero counters + detect index dtype -----------------
__global__ void k_init(const int* __restrict__ ei32, int n, int E) {
    int i = blockIdx.x * blockDim.x + threadIdx.x;
    if (i < n) g_cnt[i] = 0;
    if (blockIdx.x == 0) {
        int samples = 4096;
        if (samples > E / 2) samples = E / 2;
        int nz = 0;
        for (int s = threadIdx.x; s < samples; s += blockDim.x)
            if (ei32[2 * s + 1] != 0) nz = 1;
        nz = __syncthreads_or(nz);
        if (threadIdx.x == 0) g_is64 = nz ? 0 : 1;
    }
}

// ---------------- degree count ---------------------------------------------
__global__ void k_count(const void* __restrict__ ei, int E) {
    int e = blockIdx.x * blockDim.x + threadIdx.x;
    if (e >= E) return;
    int c = edge_idx(ei, (long long)E + e, g_is64);
    atomicAdd(&g_cnt[c], 1);
}

// ---------------- scan phase 1: per-block scan + dinv -----------------------
__global__ void __launch_bounds__(SCANB) k_scan_block(int n) {
    __shared__ int warp_sums[32];
    int tid = threadIdx.x, lane = tid & 31, wid = tid >> 5;
    int i = blockIdx.x * SCANB + tid;
    int v = (i < n) ? g_cnt[i] : 0;
    if (i < n) g_dinv[i] = rsqrtf((float)v + 1.0f); // +1 = self loop
    int x = v;
    #pragma unroll
    for (int d = 1; d < 32; d <<= 1) {
        int y = __shfl_up_sync(0xffffffffu, x, d);
        if (lane >= d) x += y;
    }
    if (lane == 31) warp_sums[wid] = x;
    __syncthreads();
    if (wid == 0) {
        int s = warp_sums[lane];
        #pragma unroll
        for (int d = 1; d < 32; d <<= 1) {
            int y = __shfl_up_sync(0xffffffffu, s, d);
            if (lane >= d) s += y;
        }
        warp_sums[lane] = s;
    }
    __syncthreads();
    int excl = x - v + (wid ? warp_sums[wid - 1] : 0);
    if (i < n) g_off[i] = excl;
    if (tid == SCANB - 1) g_bsum[blockIdx.x] = excl + v;
}

// ---------------- scan phase 2 ----------------------------------------------
__global__ void k_scan_tops(int nb, int n) {
    __shared__ int warp_sums[32];
    int tid = threadIdx.x, lane = tid & 31, wid = tid >> 5;
    int v = (tid < nb) ? g_bsum[tid] : 0;
    int x = v;
    #pragma unroll
    for (int d = 1; d < 32; d <<= 1) {
        int y = __shfl_up_sync(0xffffffffu, x, d);
        if (lane >= d) x += y;
    }
    if (lane == 31) warp_sums[wid] = x;
    __syncthreads();
    if (wid == 0) {
        int s = warp_sums[lane];
        #pragma unroll
        for (int d = 1; d < 32; d <<= 1) {
            int y = __shfl_up_sync(0xffffffffu, s, d);
            if (lane >= d) s += y;
        }
        warp_sums[lane] = s;
    }
    __syncthreads();
    int excl = x - v + (wid ? warp_sums[wid - 1] : 0);
    if (tid < nb) g_boff[tid] = excl;
    if (tid == nb - 1) g_off[n] = excl + v;
}

// ---------------- scan phase 3 ----------------------------------------------
__global__ void __launch_bounds__(SCANB) k_scan_add(int n) {
    int i = blockIdx.x * SCANB + threadIdx.x;
    if (i < n) {
        int v = g_off[i] + g_boff[blockIdx.x];
        g_off[i] = v;
        g_cur[i] = v;
    }
}

// ---------------- scatter edges into CSC -----------------------------------
__global__ void k_scatter(const void* __restrict__ ei, int E) {
    int e = blockIdx.x * blockDim.x + threadIdx.x;
    if (e >= E) return;
    int is64 = g_is64;
    int r = edge_idx(ei, e, is64);
    int c = edge_idx(ei, (long long)E + e, is64);
    int p = atomicAdd(&g_cur[c], 1);
    g_src[p] = r;
    g_w[p]   = g_dinv[r] * g_dinv[c];
}

// ---------------- GEMM1: h1 = x(Mx256) @ W1(256x128), packed f32x2 ---------
__global__ void __launch_bounds__(256) k_gemm1(const float* __restrict__ A,
                                               const float* __restrict__ B,
                                               int M) {
    __shared__ float As[16][128]; // [k][row]
    __shared__ float Bs[16][128]; // [k][col]
    const int tid  = threadIdx.x;
    const int brow = blockIdx.x * 128;
    const int tx   = tid & 15;   // col group (8 cols = 4 pairs)
    const int ty   = tid >> 4;   // row group (8 rows)

    // packed accumulators: acc2[i][j2] = (col 2*j2, col 2*j2+1) for row i
    unsigned long long acc2[8][4];
    #pragma unroll
    for (int i = 0; i < 8; i++)
        #pragma unroll
        for (int j = 0; j < 4; j++) acc2[i][j] = 0ull;

    const int a_row = tid >> 1;          // 0..127
    const int a_k   = (tid & 1) * 8;     // 0 or 8
    const int b_k   = tid >> 5;          // 0..7
    const int b_col = (tid & 31) * 4;

    for (int k0 = 0; k0 < NFEAT; k0 += 16) {
        int gr = brow + a_row;
        float4 av0 = make_float4(0.f, 0.f, 0.f, 0.f);
        float4 av1 = make_float4(0.f, 0.f, 0.f, 0.f);
        if (gr < M) {
            av0 = *reinterpret_cast<const float4*>(&A[(long long)gr * NFEAT + k0 + a_k]);
            av1 = *reinterpret_cast<const float4*>(&A[(long long)gr * NFEAT + k0 + a_k + 4]);
        }
        As[a_k + 0][a_row] = av0.x;
        As[a_k + 1][a_row] = av0.y;
        As[a_k + 2][a_row] = av0.z;
        As[a_k + 3][a_row] = av0.w;
        As[a_k + 4][a_row] = av1.x;
        As[a_k + 5][a_row] = av1.y;
        As[a_k + 6][a_row] = av1.z;
        As[a_k + 7][a_row] = av1.w;
        float4 bv0 = *reinterpret_cast<const float4*>(&B[(k0 + b_k) * NHID + b_col]);
        float4 bv1 = *reinterpret_cast<const float4*>(&B[(k0 + b_k + 8) * NHID + b_col]);
        *reinterpret_cast<float4*>(&Bs[b_k][b_col])     = bv0;
        *reinterpret_cast<float4*>(&Bs[b_k + 8][b_col]) = bv1;
        __syncthreads();
        #pragma unroll
        for (int kk = 0; kk < 16; kk++) {
            float4 a0 = *reinterpret_cast<const float4*>(&As[kk][ty * 8]);
            float4 a1 = *reinterpret_cast<const float4*>(&As[kk][ty * 8 + 4]);
            uint32_t ab[8] = {
                __float_as_uint(a0.x), __float_as_uint(a0.y),
                __float_as_uint(a0.z), __float_as_uint(a0.w),
                __float_as_uint(a1.x), __float_as_uint(a1.y),
                __float_as_uint(a1.z), __float_as_uint(a1.w)
            };
            // B pairs: 64-bit shared loads are already packed (lo=even col)
            unsigned long long bp[4];
            #pragma unroll
            for (int j = 0; j < 4; j++)
                bp[j] = *reinterpret_cast<const unsigned long long*>(&Bs[kk][tx * 8 + j * 2]);
            #pragma unroll
            for (int i = 0; i < 8; i++) {
                unsigned long long ad;
                asm("mov.b64 %0, {%1, %1};" : "=l"(ad) : "r"(ab[i]));
                #pragma unroll
                for (int j = 0; j < 4; j++)
                    asm("fma.rn.f32x2 %0, %1, %2, %0;" : "+l"(acc2[i][j]) : "l"(ad), "l"(bp[j]));
            }
        }
        __syncthreads();
    }
    #pragma unroll
    for (int i = 0; i < 8; i++) {
        int gr = brow + ty * 8 + i;
        if (gr < M) {
            float o[8];
            #pragma unroll
            for (int j = 0; j < 4; j++)
                asm("mov.b64 {%0, %1}, %2;" : "=f"(o[2 * j]), "=f"(o[2 * j + 1]) : "l"(acc2[i][j]));
            *reinterpret_cast<float4*>(&g_h1[(long long)gr * NHID + tx * 8]) =
                make_float4(o[0], o[1], o[2], o[3]);
            *reinterpret_cast<float4*>(&g_h1[(long long)gr * NHID + tx * 8 + 4]) =
                make_float4(o[4], o[5], o[6], o[7]);
        }
    }
}

// ---------------- agg1: g1 = relu(Ahat @ h1 + b1), warp per node -----------
__global__ void __launch_bounds__(256) k_agg1(const float* __restrict__ b1, int n) {
    int gtid = blockIdx.x * blockDim.x + threadIdx.x;
    int node = gtid >> 5;
    int lane = threadIdx.x & 31;
    if (node >= n) return;
    const float4* h1v = reinterpret_cast<const float4*>(g_h1);
    float dv = g_dinv[node];
    float sw = dv * dv;
    float4 hv = h1v[(long long)node * 32 + lane];
    float ax = hv.x * sw, ay = hv.y * sw, az = hv.z * sw, aw = hv.w * sw;

    int p = g_off[node], end = g_off[node + 1];
    for (; p + 1 < end; p += 2) {
        int   s0 = g_src[p],     s1 = g_src[p + 1];
        float w0 = g_w[p],       w1 = g_w[p + 1];
        float4 v0 = h1v[(long long)s0 * 32 + lane];
        float4 v1 = h1v[(long long)s1 * 32 + lane];
        ax += v0.x * w0 + v1.x * w1;
        ay += v0.y * w0 + v1.y * w1;
        az += v0.z * w0 + v1.z * w1;
        aw += v0.w * w0 + v1.w * w1;
    }
    if (p < end) {
        int s0 = g_src[p]; float w0 = g_w[p];
        float4 v0 = h1v[(long long)s0 * 32 + lane];
        ax += v0.x * w0; ay += v0.y * w0; az += v0.z * w0; aw += v0.w * w0;
    }
    float4 bb = reinterpret_cast<const float4*>(b1)[lane];
    float4 out;
    out.x = fmaxf(ax + bb.x, 0.f);
    out.y = fmaxf(ay + bb.y, 0.f);
    out.z = fmaxf(az + bb.z, 0.f);
    out.w = fmaxf(aw + bb.w, 0.f);
    reinterpret_cast<float4*>(g_g1)[(long long)node * 32 + lane] = out;
}

// ---------------- GEMM2: h2 = g1(Mx128) @ W2(128x16) -----------------------
__global__ void __launch_bounds__(256) k_gemm2(const float* __restrict__ W2, int M) {
    __shared__ float s_g[16 * 128];
    __shared__ float s_w[128 * 16];
    int node0 = blockIdx.x * 16;
    int tid = threadIdx.x;
    for (int idx = tid; idx < 2048; idx += 256) {
        s_w[idx] = W2[idx];
        int nd = idx >> 7;
        s_g[idx] = (node0 + nd < M) ? g_g1[(long long)node0 * 128 + idx] : 0.f;
    }
    __syncthreads();
    int nd = tid >> 4, j = tid & 15;
    float acc = 0.f;
    #pragma unroll
    for (int k = 0; k < 128; k++)
        acc = fmaf(s_g[nd * 128 + k], s_w[k * 16 + j], acc);
    if (node0 + nd < M)
        g_h2[(long long)(node0 + nd) * 16 + j] = acc;
}

// ---------------- agg2: out = Ahat @ h2 + b2, 16 threads per node ----------
__global__ void __launch_bounds__(256) k_agg2(const float* __restrict__ b2,
                                              float* __restrict__ out, int n) {
    int gtid = blockIdx.x * blockDim.x + threadIdx.x;
    int node = gtid >> 4;
    int lane = threadIdx.x & 15;
    if (node >= n) return;
    float dv = g_dinv[node];
    float acc = g_h2[(long long)node * 16 + lane] * dv * dv;
    int p = g_off[node], end = g_off[node + 1];
    for (; p + 1 < end; p += 2) {
        int   s0 = g_src[p], s1 = g_src[p + 1];
        float w0 = g_w[p],   w1 = g_w[p + 1];
        acc += g_h2[(long long)s0 * 16 + lane] * w0
             + g_h2[(long long)s1 * 16 + lane] * w1;
    }
    if (p < end)
        acc += g_h2[(long long)g_src[p] * 16 + lane] * g_w[p];
    out[(long long)node * 16 + lane] = acc + b2[lane];
}

// ---------------- launch ----------------------------------------------------
extern "C" void kernel_launch(void* const* d_in, const int* in_sizes, int n_in,
                              void* d_out, int out_size) {
    const float* x  = (const float*)d_in[0];
    const void*  ei = d_in[1];
    const float* W1 = (const float*)d_in[2];
    const float* b1 = (const float*)d_in[3];
    const float* W2 = (const float*)d_in[4];
    const float* b2 = (const float*)d_in[5];
    float* out = (float*)d_out;

    int n = in_sizes[0] / NFEAT;
    int E = in_sizes[1] / 2;

    int gN = (n + 255) / 256;
    int gE = (E + 255) / 256;
    int nb = (n + SCANB - 1) / SCANB;

    k_init<<<gN, 256>>>((const int*)ei, n, E);
    k_count<<<gE, 256>>>(ei, E);
    k_scan_block<<<nb, SCANB>>>(n);
    k_scan_tops<<<1, 128>>>(nb, n);
    k_scan_add<<<nb, SCANB>>>(n);
    k_scatter<<<gE, 256>>>(ei, E);
    k_gemm1<<<(n + 127) / 128, 256>>>(x, W1, n);
    k_agg1<<<(n * 32 + 255) / 256, 256>>>(b1, n);
    k_gemm2<<<(n + 15) / 16, 256>>>(W2, n);
    k_agg2<<<(n * 16 + 255) / 256, 256>>>(b2, out, n);
}

// round 5
// speedup vs baseline: 1.5778x; 1.3178x over previous
#include <cuda_runtime.h>
#include <cstdint>

#define NFEAT   256
#define NHID    128
#define NCLS    16
#define MAXN    100000
#define MAXE    1600000
#define SCANB   1024
#define MAXBLK  128

// ---------------- scratch (device globals; no allocation allowed) ----------
__device__ int   g_cnt[MAXN];
__device__ int   g_cur[MAXN];
__device__ int   g_off[MAXN + 1];
__device__ int   g_bsum[MAXBLK];
__device__ int   g_boff[MAXBLK];
__device__ float g_dinv[MAXN];
__device__ int   g_src[MAXE];
__device__ float g_w[MAXE];
__device__ float g_h1[(size_t)MAXN * NHID];
__device__ float g_g1[(size_t)MAXN * NHID];
__device__ float g_h2[(size_t)MAXN * NCLS];
__device__ int   g_is64;

// ---------------- index fetch (runtime int32/int64 dispatch) ---------------
__device__ __forceinline__ int edge_idx(const void* ei, long long pos, int is64) {
    if (is64) return (int)((const long long*)ei)[pos];
    return ((const int*)ei)[pos];
}

// ---------------- init: zero counters + detect index dtype -----------------
__global__ void k_init(const int* __restrict__ ei32, int n, int E) {
    int i = blockIdx.x * blockDim.x + threadIdx.x;
    if (i < n) g_cnt[i] = 0;
    if (blockIdx.x == 0) {
        int samples = 4096;
        if (samples > E / 2) samples = E / 2;
        int nz = 0;
        for (int s = threadIdx.x; s < samples; s += blockDim.x)
            if (ei32[2 * s + 1] != 0) nz = 1;
        nz = __syncthreads_or(nz);
        if (threadIdx.x == 0) g_is64 = nz ? 0 : 1;
    }
}

// ---------------- degree count ---------------------------------------------
__global__ void k_count(const void* __restrict__ ei, int E) {
    int e = blockIdx.x * blockDim.x + threadIdx.x;
    if (e >= E) return;
    int c = edge_idx(ei, (long long)E + e, g_is64);
    atomicAdd(&g_cnt[c], 1);
}

// ---------------- scan phase 1: per-block scan + dinv -----------------------
__global__ void __launch_bounds__(SCANB) k_scan_block(int n) {
    __shared__ int warp_sums[32];
    int tid = threadIdx.x, lane = tid & 31, wid = tid >> 5;
    int i = blockIdx.x * SCANB + tid;
    int v = (i < n) ? g_cnt[i] : 0;
    if (i < n) g_dinv[i] = rsqrtf((float)v + 1.0f); // +1 = self loop
    int x = v;
    #pragma unroll
    for (int d = 1; d < 32; d <<= 1) {
        int y = __shfl_up_sync(0xffffffffu, x, d);
        if (lane >= d) x += y;
    }
    if (lane == 31) warp_sums[wid] = x;
    __syncthreads();
    if (wid == 0) {
        int s = warp_sums[lane];
        #pragma unroll
        for (int d = 1; d < 32; d <<= 1) {
            int y = __shfl_up_sync(0xffffffffu, s, d);
            if (lane >= d) s += y;
        }
        warp_sums[lane] = s;
    }
    __syncthreads();
    int excl = x - v + (wid ? warp_sums[wid - 1] : 0);
    if (i < n) g_off[i] = excl;
    if (tid == SCANB - 1) g_bsum[blockIdx.x] = excl + v;
}

// ---------------- scan phase 2 ----------------------------------------------
__global__ void k_scan_tops(int nb, int n) {
    __shared__ int warp_sums[32];
    int tid = threadIdx.x, lane = tid & 31, wid = tid >> 5;
    int v = (tid < nb) ? g_bsum[tid] : 0;
    int x = v;
    #pragma unroll
    for (int d = 1; d < 32; d <<= 1) {
        int y = __shfl_up_sync(0xffffffffu, x, d);
        if (lane >= d) x += y;
    }
    if (lane == 31) warp_sums[wid] = x;
    __syncthreads();
    if (wid == 0) {
        int s = warp_sums[lane];
        #pragma unroll
        for (int d = 1; d < 32; d <<= 1) {
            int y = __shfl_up_sync(0xffffffffu, s, d);
            if (lane >= d) s += y;
        }
        warp_sums[lane] = s;
    }
    __syncthreads();
    int excl = x - v + (wid ? warp_sums[wid - 1] : 0);
    if (tid < nb) g_boff[tid] = excl;
    if (tid == nb - 1) g_off[n] = excl + v;
}

// ---------------- scan phase 3 ----------------------------------------------
__global__ void __launch_bounds__(SCANB) k_scan_add(int n) {
    int i = blockIdx.x * SCANB + threadIdx.x;
    if (i < n) {
        int v = g_off[i] + g_boff[blockIdx.x];
        g_off[i] = v;
        g_cur[i] = v;
    }
}

// ---------------- scatter edges into CSC -----------------------------------
__global__ void k_scatter(const void* __restrict__ ei, int E) {
    int e = blockIdx.x * blockDim.x + threadIdx.x;
    if (e >= E) return;
    int is64 = g_is64;
    int r = edge_idx(ei, e, is64);
    int c = edge_idx(ei, (long long)E + e, is64);
    int p = atomicAdd(&g_cur[c], 1);
    g_src[p] = r;
    g_w[p]   = g_dinv[r] * g_dinv[c];
}

// ---------------- tf32 helpers ----------------------------------------------
__device__ __forceinline__ uint32_t f2tf32(float f) {
    uint32_t u;
    asm("cvt.rna.tf32.f32 %0, %1;" : "=r"(u) : "f"(f));
    return u;
}
__device__ __forceinline__ void mma_tf32(float* d, const uint32_t* a, uint32_t b0, uint32_t b1) {
    asm("mma.sync.aligned.m16n8k8.row.col.f32.tf32.tf32.f32 "
        "{%0,%1,%2,%3}, {%4,%5,%6,%7}, {%8,%9}, {%0,%1,%2,%3};"
        : "+f"(d[0]), "+f"(d[1]), "+f"(d[2]), "+f"(d[3])
        : "r"(a[0]), "r"(a[1]), "r"(a[2]), "r"(a[3]), "r"(b0), "r"(b1));
}

// ---------------- GEMM1 (mma.sync tf32): h1 = x(Mx256) @ W1(256x128) -------
#define AP 20   // As row pad
#define BP 136  // Bs row pad
__global__ void __launch_bounds__(256) k_gemm1(const float* __restrict__ A,
                                               const float* __restrict__ B,
                                               int M) {
    __shared__ uint32_t As[128][AP];   // [row][k0..15] tf32 bits
    __shared__ uint32_t Bs[16][BP];    // [k][col0..127] tf32 bits
    const int tid    = threadIdx.x;
    const int lane   = tid & 31;
    const int wid    = tid >> 5;
    const int warp_m = (wid & 3) * 32;   // 4 warps along M
    const int warp_n = (wid >> 2) * 64;  // 2 warps along N
    const int brow   = blockIdx.x * 128;

    float acc[2][8][4];
    #pragma unroll
    for (int mt = 0; mt < 2; mt++)
        #pragma unroll
        for (int nt = 0; nt < 8; nt++)
            #pragma unroll
            for (int q = 0; q < 4; q++) acc[mt][nt][q] = 0.f;

    const int a_row = tid >> 1;          // 0..127
    const int a_kq  = (tid & 1) * 8;     // 0 or 8
    const int b_k   = tid >> 4;          // 0..15
    const int b_c   = (tid & 15) * 8;    // 0..120
    const int r4    = lane >> 2;         // 0..7
    const int c4    = lane & 3;          // 0..3

    for (int k0 = 0; k0 < NFEAT; k0 += 16) {
        // stage A (convert to tf32)
        int gr = brow + a_row;
        float4 v0 = make_float4(0.f, 0.f, 0.f, 0.f);
        float4 v1 = make_float4(0.f, 0.f, 0.f, 0.f);
        if (gr < M) {
            v0 = *reinterpret_cast<const float4*>(&A[(long long)gr * NFEAT + k0 + a_kq]);
            v1 = *reinterpret_cast<const float4*>(&A[(long long)gr * NFEAT + k0 + a_kq + 4]);
        }
        As[a_row][a_kq + 0] = f2tf32(v0.x);
        As[a_row][a_kq + 1] = f2tf32(v0.y);
        As[a_row][a_kq + 2] = f2tf32(v0.z);
        As[a_row][a_kq + 3] = f2tf32(v0.w);
        As[a_row][a_kq + 4] = f2tf32(v1.x);
        As[a_row][a_kq + 5] = f2tf32(v1.y);
        As[a_row][a_kq + 6] = f2tf32(v1.z);
        As[a_row][a_kq + 7] = f2tf32(v1.w);
        // stage B (convert to tf32)
        float4 w0 = *reinterpret_cast<const float4*>(&B[(k0 + b_k) * NHID + b_c]);
        float4 w1 = *reinterpret_cast<const float4*>(&B[(k0 + b_k) * NHID + b_c + 4]);
        Bs[b_k][b_c + 0] = f2tf32(w0.x);
        Bs[b_k][b_c + 1] = f2tf32(w0.y);
        Bs[b_k][b_c + 2] = f2tf32(w0.z);
        Bs[b_k][b_c + 3] = f2tf32(w0.w);
        Bs[b_k][b_c + 4] = f2tf32(w1.x);
        Bs[b_k][b_c + 5] = f2tf32(w1.y);
        Bs[b_k][b_c + 6] = f2tf32(w1.z);
        Bs[b_k][b_c + 7] = f2tf32(w1.w);
        __syncthreads();

        #pragma unroll
        for (int kc = 0; kc < 2; kc++) {
            const int kb = kc * 8;
            uint32_t afr[2][4];
            #pragma unroll
            for (int mt = 0; mt < 2; mt++) {
                int row = warp_m + mt * 16 + r4;
                afr[mt][0] = As[row][kb + c4];
                afr[mt][1] = As[row + 8][kb + c4];
                afr[mt][2] = As[row][kb + c4 + 4];
                afr[mt][3] = As[row + 8][kb + c4 + 4];
            }
            #pragma unroll
            for (int nt = 0; nt < 8; nt++) {
                int col = warp_n + nt * 8 + r4;
                uint32_t b0 = Bs[kb + c4][col];
                uint32_t b1 = Bs[kb + c4 + 4][col];
                mma_tf32(acc[0][nt], afr[0], b0, b1);
                mma_tf32(acc[1][nt], afr[1], b0, b1);
            }
        }
        __syncthreads();
    }

    // epilogue: c0:(r4, 2c4) c1:(r4, 2c4+1) c2:(r4+8, 2c4) c3:(r4+8, 2c4+1)
    #pragma unroll
    for (int mt = 0; mt < 2; mt++) {
        int row0 = brow + warp_m + mt * 16 + r4;
        #pragma unroll
        for (int nt = 0; nt < 8; nt++) {
            int col = warp_n + nt * 8 + 2 * c4;
            if (row0 < M)
                *reinterpret_cast<float2*>(&g_h1[(long long)row0 * NHID + col]) =
                    make_float2(acc[mt][nt][0], acc[mt][nt][1]);
            if (row0 + 8 < M)
                *reinterpret_cast<float2*>(&g_h1[(long long)(row0 + 8) * NHID + col]) =
                    make_float2(acc[mt][nt][2], acc[mt][nt][3]);
        }
    }
}

// ---------------- agg1: g1 = relu(Ahat @ h1 + b1), warp per node -----------
__global__ void __launch_bounds__(256) k_agg1(const float* __restrict__ b1, int n) {
    int gtid = blockIdx.x * blockDim.x + threadIdx.x;
    int node = gtid >> 5;
    int lane = threadIdx.x & 31;
    if (node >= n) return;
    const float4* h1v = reinterpret_cast<const float4*>(g_h1);
    float dv = g_dinv[node];
    float sw = dv * dv;
    float4 hv = h1v[(long long)node * 32 + lane];
    float ax = hv.x * sw, ay = hv.y * sw, az = hv.z * sw, aw = hv.w * sw;

    int p = g_off[node], end = g_off[node + 1];
    for (; p + 1 < end; p += 2) {
        int   s0 = g_src[p],     s1 = g_src[p + 1];
        float w0 = g_w[p],       w1 = g_w[p + 1];
        float4 v0 = h1v[(long long)s0 * 32 + lane];
        float4 v1 = h1v[(long long)s1 * 32 + lane];
        ax += v0.x * w0 + v1.x * w1;
        ay += v0.y * w0 + v1.y * w1;
        az += v0.z * w0 + v1.z * w1;
        aw += v0.w * w0 + v1.w * w1;
    }
    if (p < end) {
        int s0 = g_src[p]; float w0 = g_w[p];
        float4 v0 = h1v[(long long)s0 * 32 + lane];
        ax += v0.x * w0; ay += v0.y * w0; az += v0.z * w0; aw += v0.w * w0;
    }
    float4 bb = reinterpret_cast<const float4*>(b1)[lane];
    float4 out;
    out.x = fmaxf(ax + bb.x, 0.f);
    out.y = fmaxf(ay + bb.y, 0.f);
    out.z = fmaxf(az + bb.z, 0.f);
    out.w = fmaxf(aw + bb.w, 0.f);
    reinterpret_cast<float4*>(g_g1)[(long long)node * 32 + lane] = out;
}

// ---------------- GEMM2: h2 = g1(Mx128) @ W2(128x16) -----------------------
__global__ void __launch_bounds__(256) k_gemm2(const float* __restrict__ W2, int M) {
    __shared__ float s_g[16 * 128];
    __shared__ float s_w[128 * 16];
    int node0 = blockIdx.x * 16;
    int tid = threadIdx.x;
    for (int idx = tid; idx < 2048; idx += 256) {
        s_w[idx] = W2[idx];
        int nd = idx >> 7;
        s_g[idx] = (node0 + nd < M) ? g_g1[(long long)node0 * 128 + idx] : 0.f;
    }
    __syncthreads();
    int nd = tid >> 4, j = tid & 15;
    float acc = 0.f;
    #pragma unroll
    for (int k = 0; k < 128; k++)
        acc = fmaf(s_g[nd * 128 + k], s_w[k * 16 + j], acc);
    if (node0 + nd < M)
        g_h2[(long long)(node0 + nd) * 16 + j] = acc;
}

// ---------------- agg2: out = Ahat @ h2 + b2, 16 threads per node ----------
__global__ void __launch_bounds__(256) k_agg2(const float* __restrict__ b2,
                                              float* __restrict__ out, int n) {
    int gtid = blockIdx.x * blockDim.x + threadIdx.x;
    int node = gtid >> 4;
    int lane = threadIdx.x & 15;
    if (node >= n) return;
    float dv = g_dinv[node];
    float acc = g_h2[(long long)node * 16 + lane] * dv * dv;
    int p = g_off[node], end = g_off[node + 1];
    for (; p + 1 < end; p += 2) {
        int   s0 = g_src[p], s1 = g_src[p + 1];
        float w0 = g_w[p],   w1 = g_w[p + 1];
        acc += g_h2[(long long)s0 * 16 + lane] * w0
             + g_h2[(long long)s1 * 16 + lane] * w1;
    }
    if (p < end)
        acc += g_h2[(long long)g_src[p] * 16 + lane] * g_w[p];
    out[(long long)node * 16 + lane] = acc + b2[lane];
}

// ---------------- launch ----------------------------------------------------
extern "C" void kernel_launch(void* const* d_in, const int* in_sizes, int n_in,
                              void* d_out, int out_size) {
    const float* x  = (const float*)d_in[0];
    const void*  ei = d_in[1];
    const float* W1 = (const float*)d_in[2];
    const float* b1 = (const float*)d_in[3];
    const float* W2 = (const float*)d_in[4];
    const float* b2 = (const float*)d_in[5];
    float* out = (float*)d_out;

    int n = in_sizes[0] / NFEAT;
    int E = in_sizes[1] / 2;

    int gN = (n + 255) / 256;
    int gE = (E + 255) / 256;
    int nb = (n + SCANB - 1) / SCANB;

    k_init<<<gN, 256>>>((const int*)ei, n, E);
    k_count<<<gE, 256>>>(ei, E);
    k_scan_block<<<nb, SCANB>>>(n);
    k_scan_tops<<<1, 128>>>(nb, n);
    k_scan_add<<<nb, SCANB>>>(n);
    k_scatter<<<gE, 256>>>(ei, E);
    k_gemm1<<<(n + 127) / 128, 256>>>(x, W1, n);
    k_agg1<<<(n * 32 + 255) / 256, 256>>>(b1, n);
    k_gemm2<<<(n + 15) / 16, 256>>>(W2, n);
    k_agg2<<<(n * 16 + 255) / 256, 256>>>(b2, out, n);
}

// round 6
// speedup vs baseline: 1.7499x; 1.1090x over previous
#include <cuda_runtime.h>
#include <cstdint>

#define NFEAT   256
#define NHID    128
#define NCLS    16
#define MAXN    100000
#define MAXE    1600000
#define SCANB   1024
#define MAXBLK  128

// ---------------- scratch (device globals; no allocation allowed) ----------
__device__ int   g_cnt[MAXN];
__device__ int   g_cur[MAXN];
__device__ int   g_off[MAXN + 1];
__device__ int   g_bsum[MAXBLK];
__device__ int   g_boff[MAXBLK];
__device__ float g_dinv[MAXN];
__device__ int   g_src[MAXE];
__device__ float g_w[MAXE];
__device__ float g_h1[(size_t)MAXN * NHID];
__device__ float g_g1[(size_t)MAXN * NHID];
__device__ float g_h2[(size_t)MAXN * NCLS];
__device__ int   g_is64;

// ---------------- index fetch (runtime int32/int64 dispatch) ---------------
__device__ __forceinline__ int edge_idx(const void* ei, long long pos, int is64) {
    if (is64) return (int)((const long long*)ei)[pos];
    return ((const int*)ei)[pos];
}

// ---------------- init: zero counters + detect index dtype -----------------
__global__ void k_init(const int* __restrict__ ei32, int n, int E) {
    int i = blockIdx.x * blockDim.x + threadIdx.x;
    if (i < n) g_cnt[i] = 0;
    if (blockIdx.x == 0) {
        int samples = 4096;
        if (samples > E / 2) samples = E / 2;
        int nz = 0;
        for (int s = threadIdx.x; s < samples; s += blockDim.x)
            if (ei32[2 * s + 1] != 0) nz = 1;
        nz = __syncthreads_or(nz);
        if (threadIdx.x == 0) g_is64 = nz ? 0 : 1;
    }
}

// ---------------- degree count ---------------------------------------------
__global__ void k_count(const void* __restrict__ ei, int E) {
    int e = blockIdx.x * blockDim.x + threadIdx.x;
    if (e >= E) return;
    int c = edge_idx(ei, (long long)E + e, g_is64);
    atomicAdd(&g_cnt[c], 1);
}

// ---------------- scan phase 1: per-block scan + dinv -----------------------
__global__ void __launch_bounds__(SCANB) k_scan_block(int n) {
    __shared__ int warp_sums[32];
    int tid = threadIdx.x, lane = tid & 31, wid = tid >> 5;
    int i = blockIdx.x * SCANB + tid;
    int v = (i < n) ? g_cnt[i] : 0;
    if (i < n) g_dinv[i] = rsqrtf((float)v + 1.0f); // +1 = self loop
    int x = v;
    #pragma unroll
    for (int d = 1; d < 32; d <<= 1) {
        int y = __shfl_up_sync(0xffffffffu, x, d);
        if (lane >= d) x += y;
    }
    if (lane == 31) warp_sums[wid] = x;
    __syncthreads();
    if (wid == 0) {
        int s = warp_sums[lane];
        #pragma unroll
        for (int d = 1; d < 32; d <<= 1) {
            int y = __shfl_up_sync(0xffffffffu, s, d);
            if (lane >= d) s += y;
        }
        warp_sums[lane] = s;
    }
    __syncthreads();
    int excl = x - v + (wid ? warp_sums[wid - 1] : 0);
    if (i < n) g_off[i] = excl;
    if (tid == SCANB - 1) g_bsum[blockIdx.x] = excl + v;
}

// ---------------- scan phase 2 ----------------------------------------------
__global__ void k_scan_tops(int nb, int n) {
    __shared__ int warp_sums[32];
    int tid = threadIdx.x, lane = tid & 31, wid = tid >> 5;
    int v = (tid < nb) ? g_bsum[tid] : 0;
    int x = v;
    #pragma unroll
    for (int d = 1; d < 32; d <<= 1) {
        int y = __shfl_up_sync(0xffffffffu, x, d);
        if (lane >= d) x += y;
    }
    if (lane == 31) warp_sums[wid] = x;
    __syncthreads();
    if (wid == 0) {
        int s = warp_sums[lane];
        #pragma unroll
        for (int d = 1; d < 32; d <<= 1) {
            int y = __shfl_up_sync(0xffffffffu, s, d);
            if (lane >= d) s += y;
        }
        warp_sums[lane] = s;
    }
    __syncthreads();
    int excl = x - v + (wid ? warp_sums[wid - 1] : 0);
    if (tid < nb) g_boff[tid] = excl;
    if (tid == nb - 1) g_off[n] = excl + v;
}

// ---------------- scan phase 3 ----------------------------------------------
__global__ void __launch_bounds__(SCANB) k_scan_add(int n) {
    int i = blockIdx.x * SCANB + threadIdx.x;
    if (i < n) {
        int v = g_off[i] + g_boff[blockIdx.x];
        g_off[i] = v;
        g_cur[i] = v;
    }
}

// ---------------- scatter edges into CSC -----------------------------------
__global__ void k_scatter(const void* __restrict__ ei, int E) {
    int e = blockIdx.x * blockDim.x + threadIdx.x;
    if (e >= E) return;
    int is64 = g_is64;
    int r = edge_idx(ei, e, is64);
    int c = edge_idx(ei, (long long)E + e, is64);
    int p = atomicAdd(&g_cur[c], 1);
    g_src[p] = r;
    g_w[p]   = g_dinv[r] * g_dinv[c];
}

// ---------------- tf32 helpers ----------------------------------------------
__device__ __forceinline__ uint32_t f2tf32(float f) {
    uint32_t u;
    asm("cvt.rna.tf32.f32 %0, %1;" : "=r"(u) : "f"(f));
    return u;
}
__device__ __forceinline__ void mma_tf32(float* d, const uint32_t* a, uint32_t b0, uint32_t b1) {
    asm("mma.sync.aligned.m16n8k8.row.col.f32.tf32.tf32.f32 "
        "{%0,%1,%2,%3}, {%4,%5,%6,%7}, {%8,%9}, {%0,%1,%2,%3};"
        : "+f"(d[0]), "+f"(d[1]), "+f"(d[2]), "+f"(d[3])
        : "r"(a[0]), "r"(a[1]), "r"(a[2]), "r"(a[3]), "r"(b0), "r"(b1));
}

// ---------------- GEMM1 (mma.sync tf32): h1 = x(Mx256) @ W1(256x128) -------
#define AP 20   // As row pad
#define BP 136  // Bs row pad
__global__ void __launch_bounds__(256) k_gemm1(const float* __restrict__ A,
                                               const float* __restrict__ B,
                                               int M) {
    __shared__ uint32_t As[128][AP];   // [row][k0..15] tf32 bits
    __shared__ uint32_t Bs[16][BP];    // [k][col0..127] tf32 bits
    const int tid    = threadIdx.x;
    const int lane   = tid & 31;
    const int wid    = tid >> 5;
    const int warp_m = (wid & 3) * 32;   // 4 warps along M
    const int warp_n = (wid >> 2) * 64;  // 2 warps along N
    const int brow   = blockIdx.x * 128;

    float acc[2][8][4];
    #pragma unroll
    for (int mt = 0; mt < 2; mt++)
        #pragma unroll
        for (int nt = 0; nt < 8; nt++)
            #pragma unroll
            for (int q = 0; q < 4; q++) acc[mt][nt][q] = 0.f;

    const int a_row = tid >> 1;          // 0..127
    const int a_kq  = (tid & 1) * 8;     // 0 or 8
    const int b_k   = tid >> 4;          // 0..15
    const int b_c   = (tid & 15) * 8;    // 0..120
    const int r4    = lane >> 2;         // 0..7
    const int c4    = lane & 3;          // 0..3

    for (int k0 = 0; k0 < NFEAT; k0 += 16) {
        // stage A (convert to tf32)
        int gr = brow + a_row;
        float4 v0 = make_float4(0.f, 0.f, 0.f, 0.f);
        float4 v1 = make_float4(0.f, 0.f, 0.f, 0.f);
        if (gr < M) {
            v0 = *reinterpret_cast<const float4*>(&A[(long long)gr * NFEAT + k0 + a_kq]);
            v1 = *reinterpret_cast<const float4*>(&A[(long long)gr * NFEAT + k0 + a_kq + 4]);
        }
        As[a_row][a_kq + 0] = f2tf32(v0.x);
        As[a_row][a_kq + 1] = f2tf32(v0.y);
        As[a_row][a_kq + 2] = f2tf32(v0.z);
        As[a_row][a_kq + 3] = f2tf32(v0.w);
        As[a_row][a_kq + 4] = f2tf32(v1.x);
        As[a_row][a_kq + 5] = f2tf32(v1.y);
        As[a_row][a_kq + 6] = f2tf32(v1.z);
        As[a_row][a_kq + 7] = f2tf32(v1.w);
        // stage B (convert to tf32)
        float4 w0 = *reinterpret_cast<const float4*>(&B[(k0 + b_k) * NHID + b_c]);
        float4 w1 = *reinterpret_cast<const float4*>(&B[(k0 + b_k) * NHID + b_c + 4]);
        Bs[b_k][b_c + 0] = f2tf32(w0.x);
        Bs[b_k][b_c + 1] = f2tf32(w0.y);
        Bs[b_k][b_c + 2] = f2tf32(w0.z);
        Bs[b_k][b_c + 3] = f2tf32(w0.w);
        Bs[b_k][b_c + 4] = f2tf32(w1.x);
        Bs[b_k][b_c + 5] = f2tf32(w1.y);
        Bs[b_k][b_c + 6] = f2tf32(w1.z);
        Bs[b_k][b_c + 7] = f2tf32(w1.w);
        __syncthreads();

        #pragma unroll
        for (int kc = 0; kc < 2; kc++) {
            const int kb = kc * 8;
            uint32_t afr[2][4];
            #pragma unroll
            for (int mt = 0; mt < 2; mt++) {
                int row = warp_m + mt * 16 + r4;
                afr[mt][0] = As[row][kb + c4];
                afr[mt][1] = As[row + 8][kb + c4];
                afr[mt][2] = As[row][kb + c4 + 4];
                afr[mt][3] = As[row + 8][kb + c4 + 4];
            }
            #pragma unroll
            for (int nt = 0; nt < 8; nt++) {
                int col = warp_n + nt * 8 + r4;
                uint32_t b0 = Bs[kb + c4][col];
                uint32_t b1 = Bs[kb + c4 + 4][col];
                mma_tf32(acc[0][nt], afr[0], b0, b1);
                mma_tf32(acc[1][nt], afr[1], b0, b1);
            }
        }
        __syncthreads();
    }

    // epilogue
    #pragma unroll
    for (int mt = 0; mt < 2; mt++) {
        int row0 = brow + warp_m + mt * 16 + r4;
        #pragma unroll
        for (int nt = 0; nt < 8; nt++) {
            int col = warp_n + nt * 8 + 2 * c4;
            if (row0 < M)
                *reinterpret_cast<float2*>(&g_h1[(long long)row0 * NHID + col]) =
                    make_float2(acc[mt][nt][0], acc[mt][nt][1]);
            if (row0 + 8 < M)
                *reinterpret_cast<float2*>(&g_h1[(long long)(row0 + 8) * NHID + col]) =
                    make_float2(acc[mt][nt][2], acc[mt][nt][3]);
        }
    }
}

// ---------------- agg1: g1 = relu(Ahat @ h1 + b1), warp per node -----------
__global__ void __launch_bounds__(256) k_agg1(const float* __restrict__ b1, int n) {
    int gtid = blockIdx.x * blockDim.x + threadIdx.x;
    int node = gtid >> 5;
    int lane = threadIdx.x & 31;
    if (node >= n) return;
    const float4* h1v = reinterpret_cast<const float4*>(g_h1);
    float dv = g_dinv[node];
    float sw = dv * dv;
    float4 hv = h1v[(long long)node * 32 + lane];
    float ax = hv.x * sw, ay = hv.y * sw, az = hv.z * sw, aw = hv.w * sw;

    int p = g_off[node], end = g_off[node + 1];
    for (; p + 3 < end; p += 4) {
        int   s0 = g_src[p],     s1 = g_src[p + 1];
        int   s2 = g_src[p + 2], s3 = g_src[p + 3];
        float w0 = g_w[p],       w1 = g_w[p + 1];
        float w2 = g_w[p + 2],   w3 = g_w[p + 3];
        float4 v0 = h1v[(long long)s0 * 32 + lane];
        float4 v1 = h1v[(long long)s1 * 32 + lane];
        float4 v2 = h1v[(long long)s2 * 32 + lane];
        float4 v3 = h1v[(long long)s3 * 32 + lane];
        ax += v0.x * w0 + v1.x * w1 + v2.x * w2 + v3.x * w3;
        ay += v0.y * w0 + v1.y * w1 + v2.y * w2 + v3.y * w3;
        az += v0.z * w0 + v1.z * w1 + v2.z * w2 + v3.z * w3;
        aw += v0.w * w0 + v1.w * w1 + v2.w * w2 + v3.w * w3;
    }
    for (; p < end; p++) {
        int s0 = g_src[p]; float w0 = g_w[p];
        float4 v0 = h1v[(long long)s0 * 32 + lane];
        ax += v0.x * w0; ay += v0.y * w0; az += v0.z * w0; aw += v0.w * w0;
    }
    float4 bb = reinterpret_cast<const float4*>(b1)[lane];
    float4 out;
    out.x = fmaxf(ax + bb.x, 0.f);
    out.y = fmaxf(ay + bb.y, 0.f);
    out.z = fmaxf(az + bb.z, 0.f);
    out.w = fmaxf(aw + bb.w, 0.f);
    reinterpret_cast<float4*>(g_g1)[(long long)node * 32 + lane] = out;
}

// ---------------- GEMM2: h2 = g1(Mx128) @ W2(128x16), reg-blocked ----------
// CTA: 128 nodes x 16 cols; 128 threads; thread: 4 nodes x 4 cols.
#define GP 68    // s_g row pad (floats)
#define WP 132   // s_wt row pad (floats)
__global__ void __launch_bounds__(128) k_gemm2(const float* __restrict__ W2, int M) {
    __shared__ float s_g[128][GP];   // [node][k-chunk 64]
    __shared__ float s_wt[16][WP];   // [col][k 0..127] transposed W2
    const int tid  = threadIdx.x;
    const int ng   = tid >> 2;       // node group 0..31 (4 nodes each)
    const int cg   = tid & 3;        // col group 0..3 (4 cols each)
    const int node0 = blockIdx.x * 128;

    // stage W2 transposed: s_wt[j][k] = W2[k*16+j]
    for (int idx = tid; idx < 2048; idx += 128) {
        int k = idx >> 4, j = idx & 15;
        s_wt[j][k] = W2[idx];
    }

    float acc[4][4];
    #pragma unroll
    for (int m = 0; m < 4; m++)
        #pragma unroll
        for (int j = 0; j < 4; j++) acc[m][j] = 0.f;

    #pragma unroll
    for (int kc = 0; kc < 2; kc++) {
        const int k0 = kc * 64;
        // stage g1 chunk: 128 nodes x 64 floats
        __syncthreads();
        #pragma unroll
        for (int i = 0; i < 16; i++) {
            int idx = i * 128 + tid;
            int nd = idx >> 4, kq = idx & 15;
            float4 v = make_float4(0.f, 0.f, 0.f, 0.f);
            if (node0 + nd < M)
                v = *reinterpret_cast<const float4*>(&g_g1[(long long)(node0 + nd) * NHID + k0 + kq * 4]);
            *reinterpret_cast<float4*>(&s_g[nd][kq * 4]) = v;
        }
        __syncthreads();
        #pragma unroll
        for (int kq = 0; kq < 16; kq++) {
            float4 a[4], b[4];
            #pragma unroll
            for (int m = 0; m < 4; m++)
                a[m] = *reinterpret_cast<const float4*>(&s_g[ng * 4 + m][kq * 4]);
            #pragma unroll
            for (int j = 0; j < 4; j++)
                b[j] = *reinterpret_cast<const float4*>(&s_wt[cg * 4 + j][k0 + kq * 4]);
            #pragma unroll
            for (int m = 0; m < 4; m++)
                #pragma unroll
                for (int j = 0; j < 4; j++)
                    acc[m][j] += a[m].x * b[j].x + a[m].y * b[j].y
                               + a[m].z * b[j].z + a[m].w * b[j].w;
        }
    }

    #pragma unroll
    for (int m = 0; m < 4; m++) {
        int nd = node0 + ng * 4 + m;
        if (nd < M)
            *reinterpret_cast<float4*>(&g_h2[(long long)nd * 16 + cg * 4]) =
                make_float4(acc[m][0], acc[m][1], acc[m][2], acc[m][3]);
    }
}

// ---------------- agg2: out = Ahat @ h2 + b2, 16 threads per node ----------
__global__ void __launch_bounds__(256) k_agg2(const float* __restrict__ b2,
                                              float* __restrict__ out, int n) {
    int gtid = blockIdx.x * blockDim.x + threadIdx.x;
    int node = gtid >> 4;
    int lane = threadIdx.x & 15;
    if (node >= n) return;
    float dv = g_dinv[node];
    float acc = g_h2[(long long)node * 16 + lane] * dv * dv;
    int p = g_off[node], end = g_off[node + 1];
    for (; p + 3 < end; p += 4) {
        int   s0 = g_src[p],     s1 = g_src[p + 1];
        int   s2 = g_src[p + 2], s3 = g_src[p + 3];
        float w0 = g_w[p],       w1 = g_w[p + 1];
        float w2 = g_w[p + 2],   w3 = g_w[p + 3];
        acc += g_h2[(long long)s0 * 16 + lane] * w0
             + g_h2[(long long)s1 * 16 + lane] * w1
             + g_h2[(long long)s2 * 16 + lane] * w2
             + g_h2[(long long)s3 * 16 + lane] * w3;
    }
    for (; p < end; p++)
        acc += g_h2[(long long)g_src[p] * 16 + lane] * g_w[p];
    out[(long long)node * 16 + lane] = acc + b2[lane];
}

// ---------------- launch ----------------------------------------------------
extern "C" void kernel_launch(void* const* d_in, const int* in_sizes, int n_in,
                              void* d_out, int out_size) {
    const float* x  = (const float*)d_in[0];
    const void*  ei = d_in[1];
    const float* W1 = (const float*)d_in[2];
    const float* b1 = (const float*)d_in[3];
    const float* W2 = (const float*)d_in[4];
    const float* b2 = (const float*)d_in[5];
    float* out = (float*)d_out;

    int n = in_sizes[0] / NFEAT;
    int E = in_sizes[1] / 2;

    int gN = (n + 255) / 256;
    int gE = (E + 255) / 256;
    int nb = (n + SCANB - 1) / SCANB;

    k_init<<<gN, 256>>>((const int*)ei, n, E);
    k_count<<<gE, 256>>>(ei, E);
    k_scan_block<<<nb, SCANB>>>(n);
    k_scan_tops<<<1, 128>>>(nb, n);
    k_scan_add<<<nb, SCANB>>>(n);
    k_scatter<<<gE, 256>>>(ei, E);
    k_gemm1<<<(n + 127) / 128, 256>>>(x, W1, n);
    k_agg1<<<(n * 32 + 255) / 256, 256>>>(b1, n);
    k_gemm2<<<(n + 127) / 128, 128>>>(W2, n);
    k_agg2<<<(n * 16 + 255) / 256, 256>>>(b2, out, n);
}

// round 7
// speedup vs baseline: 1.8694x; 1.0683x over previous
#include <cuda_runtime.h>
#include <cstdint>

#define NFEAT   256
#define NHID    128
#define NCLS    16
#define MAXN    100000
#define MAXE    1600000
#define SCANB   1024
#define MAXBLK  128

// ---------------- scratch (device globals; no allocation allowed) ----------
__device__ int   g_cnt[MAXN];
__device__ int   g_cur[MAXN];
__device__ int   g_off[MAXN + 1];
__device__ int   g_bsum[MAXBLK];
__device__ int   g_boff[MAXBLK];
__device__ float g_dinv[MAXN];
__device__ int2  g_edge[MAXE];             // x = src node, y = weight bits
__device__ float g_h1[(size_t)MAXN * NHID];
__device__ float g_g1[(size_t)MAXN * NHID];
__device__ float g_h2[(size_t)MAXN * NCLS];
__device__ int   g_is64;

// ---------------- static host context: fork-join stream + events -----------
struct HxCtx {
    cudaStream_t s2;
    cudaEvent_t  evA, evB;
    bool ok;
    HxCtx() : ok(false) {
        if (cudaStreamCreateWithFlags(&s2, cudaStreamNonBlocking) != cudaSuccess) return;
        if (cudaEventCreateWithFlags(&evA, cudaEventDisableTiming) != cudaSuccess) return;
        if (cudaEventCreateWithFlags(&evB, cudaEventDisableTiming) != cudaSuccess) return;
        ok = true;
    }
};
static HxCtx g_hx;

// ---------------- index fetch (runtime int32/int64 dispatch) ---------------
__device__ __forceinline__ int edge_idx(const void* ei, long long pos, int is64) {
    if (is64) return (int)((const long long*)ei)[pos];
    return ((const int*)ei)[pos];
}

// ---------------- init: zero counters + detect index dtype -----------------
__global__ void k_init(const int* __restrict__ ei32, int n, int E) {
    int i = blockIdx.x * blockDim.x + threadIdx.x;
    if (i < n) g_cnt[i] = 0;
    if (blockIdx.x == 0) {
        int samples = 4096;
        if (samples > E / 2) samples = E / 2;
        int nz = 0;
        for (int s = threadIdx.x; s < samples; s += blockDim.x)
            if (ei32[2 * s + 1] != 0) nz = 1;
        nz = __syncthreads_or(nz);
        if (threadIdx.x == 0) g_is64 = nz ? 0 : 1;
    }
}

// ---------------- degree count ---------------------------------------------
__global__ void k_count(const void* __restrict__ ei, int E) {
    int e = blockIdx.x * blockDim.x + threadIdx.x;
    if (e >= E) return;
    int c = edge_idx(ei, (long long)E + e, g_is64);
    atomicAdd(&g_cnt[c], 1);
}

// ---------------- scan phase 1: per-block scan + dinv -----------------------
__global__ void __launch_bounds__(SCANB) k_scan_block(int n) {
    __shared__ int warp_sums[32];
    int tid = threadIdx.x, lane = tid & 31, wid = tid >> 5;
    int i = blockIdx.x * SCANB + tid;
    int v = (i < n) ? g_cnt[i] : 0;
    if (i < n) g_dinv[i] = rsqrtf((float)v + 1.0f); // +1 = self loop
    int x = v;
    #pragma unroll
    for (int d = 1; d < 32; d <<= 1) {
        int y = __shfl_up_sync(0xffffffffu, x, d);
        if (lane >= d) x += y;
    }
    if (lane == 31) warp_sums[wid] = x;
    __syncthreads();
    if (wid == 0) {
        int s = warp_sums[lane];
        #pragma unroll
        for (int d = 1; d < 32; d <<= 1) {
            int y = __shfl_up_sync(0xffffffffu, s, d);
            if (lane >= d) s += y;
        }
        warp_sums[lane] = s;
    }
    __syncthreads();
    int excl = x - v + (wid ? warp_sums[wid - 1] : 0);
    if (i < n) g_off[i] = excl;
    if (tid == SCANB - 1) g_bsum[blockIdx.x] = excl + v;
}

// ---------------- scan phase 2 ----------------------------------------------
__global__ void k_scan_tops(int nb, int n) {
    __shared__ int warp_sums[32];
    int tid = threadIdx.x, lane = tid & 31, wid = tid >> 5;
    int v = (tid < nb) ? g_bsum[tid] : 0;
    int x = v;
    #pragma unroll
    for (int d = 1; d < 32; d <<= 1) {
        int y = __shfl_up_sync(0xffffffffu, x, d);
        if (lane >= d) x += y;
    }
    if (lane == 31) warp_sums[wid] = x;
    __syncthreads();
    if (wid == 0) {
        int s = warp_sums[lane];
        #pragma unroll
        for (int d = 1; d < 32; d <<= 1) {
            int y = __shfl_up_sync(0xffffffffu, s, d);
            if (lane >= d) s += y;
        }
        warp_sums[lane] = s;
    }
    __syncthreads();
    int excl = x - v + (wid ? warp_sums[wid - 1] : 0);
    if (tid < nb) g_boff[tid] = excl;
    if (tid == nb - 1) g_off[n] = excl + v;
}

// ---------------- scan phase 3 ----------------------------------------------
__global__ void __launch_bounds__(SCANB) k_scan_add(int n) {
    int i = blockIdx.x * SCANB + threadIdx.x;
    if (i < n) {
        int v = g_off[i] + g_boff[blockIdx.x];
        g_off[i] = v;
        g_cur[i] = v;
    }
}

// ---------------- scatter edges into CSC (interleaved src+w) ---------------
__global__ void k_scatter(const void* __restrict__ ei, int E) {
    int e = blockIdx.x * blockDim.x + threadIdx.x;
    if (e >= E) return;
    int is64 = g_is64;
    int r = edge_idx(ei, e, is64);
    int c = edge_idx(ei, (long long)E + e, is64);
    int p = atomicAdd(&g_cur[c], 1);
    g_edge[p] = make_int2(r, __float_as_int(g_dinv[r] * g_dinv[c]));
}

// ---------------- tf32 helpers ----------------------------------------------
__device__ __forceinline__ uint32_t f2tf32(float f) {
    uint32_t u;
    asm("cvt.rna.tf32.f32 %0, %1;" : "=r"(u) : "f"(f));
    return u;
}
__device__ __forceinline__ void mma_tf32(float* d, const uint32_t* a, uint32_t b0, uint32_t b1) {
    asm("mma.sync.aligned.m16n8k8.row.col.f32.tf32.tf32.f32 "
        "{%0,%1,%2,%3}, {%4,%5,%6,%7}, {%8,%9}, {%0,%1,%2,%3};"
        : "+f"(d[0]), "+f"(d[1]), "+f"(d[2]), "+f"(d[3])
        : "r"(a[0]), "r"(a[1]), "r"(a[2]), "r"(a[3]), "r"(b0), "r"(b1));
}

// ---------------- GEMM1 (mma.sync tf32): h1 = x(Mx256) @ W1(256x128) -------
#define AP 20   // As row pad
#define BP 136  // Bs row pad
__global__ void __launch_bounds__(256) k_gemm1(const float* __restrict__ A,
                                               const float* __restrict__ B,
                                               int M) {
    __shared__ uint32_t As[128][AP];   // [row][k0..15] tf32 bits
    __shared__ uint32_t Bs[16][BP];    // [k][col0..127] tf32 bits
    const int tid    = threadIdx.x;
    const int lane   = tid & 31;
    const int wid    = tid >> 5;
    const int warp_m = (wid & 3) * 32;   // 4 warps along M
    const int warp_n = (wid >> 2) * 64;  // 2 warps along N
    const int brow   = blockIdx.x * 128;

    float acc[2][8][4];
    #pragma unroll
    for (int mt = 0; mt < 2; mt++)
        #pragma unroll
        for (int nt = 0; nt < 8; nt++)
            #pragma unroll
            for (int q = 0; q < 4; q++) acc[mt][nt][q] = 0.f;

    const int a_row = tid >> 1;          // 0..127
    const int a_kq  = (tid & 1) * 8;     // 0 or 8
    const int b_k   = tid >> 4;          // 0..15
    const int b_c   = (tid & 15) * 8;    // 0..120
    const int r4    = lane >> 2;         // 0..7
    const int c4    = lane & 3;          // 0..3

    for (int k0 = 0; k0 < NFEAT; k0 += 16) {
        // stage A (convert to tf32)
        int gr = brow + a_row;
        float4 v0 = make_float4(0.f, 0.f, 0.f, 0.f);
        float4 v1 = make_float4(0.f, 0.f, 0.f, 0.f);
        if (gr < M) {
            v0 = *reinterpret_cast<const float4*>(&A[(long long)gr * NFEAT + k0 + a_kq]);
            v1 = *reinterpret_cast<const float4*>(&A[(long long)gr * NFEAT + k0 + a_kq + 4]);
        }
        As[a_row][a_kq + 0] = f2tf32(v0.x);
        As[a_row][a_kq + 1] = f2tf32(v0.y);
        As[a_row][a_kq + 2] = f2tf32(v0.z);
        As[a_row][a_kq + 3] = f2tf32(v0.w);
        As[a_row][a_kq + 4] = f2tf32(v1.x);
        As[a_row][a_kq + 5] = f2tf32(v1.y);
        As[a_row][a_kq + 6] = f2tf32(v1.z);
        As[a_row][a_kq + 7] = f2tf32(v1.w);
        // stage B (convert to tf32)
        float4 w0 = *reinterpret_cast<const float4*>(&B[(k0 + b_k) * NHID + b_c]);
        float4 w1 = *reinterpret_cast<const float4*>(&B[(k0 + b_k) * NHID + b_c + 4]);
        Bs[b_k][b_c + 0] = f2tf32(w0.x);
        Bs[b_k][b_c + 1] = f2tf32(w0.y);
        Bs[b_k][b_c + 2] = f2tf32(w0.z);
        Bs[b_k][b_c + 3] = f2tf32(w0.w);
        Bs[b_k][b_c + 4] = f2tf32(w1.x);
        Bs[b_k][b_c + 5] = f2tf32(w1.y);
        Bs[b_k][b_c + 6] = f2tf32(w1.z);
        Bs[b_k][b_c + 7] = f2tf32(w1.w);
        __syncthreads();

        #pragma unroll
        for (int kc = 0; kc < 2; kc++) {
            const int kb = kc * 8;
            uint32_t afr[2][4];
            #pragma unroll
            for (int mt = 0; mt < 2; mt++) {
                int row = warp_m + mt * 16 + r4;
                afr[mt][0] = As[row][kb + c4];
                afr[mt][1] = As[row + 8][kb + c4];
                afr[mt][2] = As[row][kb + c4 + 4];
                afr[mt][3] = As[row + 8][kb + c4 + 4];
            }
            #pragma unroll
            for (int nt = 0; nt < 8; nt++) {
                int col = warp_n + nt * 8 + r4;
                uint32_t b0 = Bs[kb + c4][col];
                uint32_t b1 = Bs[kb + c4 + 4][col];
                mma_tf32(acc[0][nt], afr[0], b0, b1);
                mma_tf32(acc[1][nt], afr[1], b0, b1);
            }
        }
        __syncthreads();
    }

    // epilogue
    #pragma unroll
    for (int mt = 0; mt < 2; mt++) {
        int row0 = brow + warp_m + mt * 16 + r4;
        #pragma unroll
        for (int nt = 0; nt < 8; nt++) {
            int col = warp_n + nt * 8 + 2 * c4;
            if (row0 < M)
                *reinterpret_cast<float2*>(&g_h1[(long long)row0 * NHID + col]) =
                    make_float2(acc[mt][nt][0], acc[mt][nt][1]);
            if (row0 + 8 < M)
                *reinterpret_cast<float2*>(&g_h1[(long long)(row0 + 8) * NHID + col]) =
                    make_float2(acc[mt][nt][2], acc[mt][nt][3]);
        }
    }
}

// ---------------- agg1: g1 = relu(Ahat @ h1 + b1), warp per node -----------
__global__ void __launch_bounds__(256) k_agg1(const float* __restrict__ b1, int n) {
    int gtid = blockIdx.x * blockDim.x + threadIdx.x;
    int node = gtid >> 5;
    int lane = threadIdx.x & 31;
    if (node >= n) return;
    const float4* h1v = reinterpret_cast<const float4*>(g_h1);
    float dv = g_dinv[node];
    float sw = dv * dv;
    float4 hv = h1v[(long long)node * 32 + lane];
    float ax = hv.x * sw, ay = hv.y * sw, az = hv.z * sw, aw = hv.w * sw;

    int p = g_off[node], end = g_off[node + 1];
    for (; p + 3 < end; p += 4) {
        int2 e0 = g_edge[p],     e1 = g_edge[p + 1];
        int2 e2 = g_edge[p + 2], e3 = g_edge[p + 3];
        float w0 = __int_as_float(e0.y), w1 = __int_as_float(e1.y);
        float w2 = __int_as_float(e2.y), w3 = __int_as_float(e3.y);
        float4 v0 = h1v[(long long)e0.x * 32 + lane];
        float4 v1 = h1v[(long long)e1.x * 32 + lane];
        float4 v2 = h1v[(long long)e2.x * 32 + lane];
        float4 v3 = h1v[(long long)e3.x * 32 + lane];
        ax += v0.x * w0 + v1.x * w1 + v2.x * w2 + v3.x * w3;
        ay += v0.y * w0 + v1.y * w1 + v2.y * w2 + v3.y * w3;
        az += v0.z * w0 + v1.z * w1 + v2.z * w2 + v3.z * w3;
        aw += v0.w * w0 + v1.w * w1 + v2.w * w2 + v3.w * w3;
    }
    for (; p < end; p++) {
        int2 e0 = g_edge[p];
        float w0 = __int_as_float(e0.y);
        float4 v0 = h1v[(long long)e0.x * 32 + lane];
        ax += v0.x * w0; ay += v0.y * w0; az += v0.z * w0; aw += v0.w * w0;
    }
    float4 bb = reinterpret_cast<const float4*>(b1)[lane];
    float4 out;
    out.x = fmaxf(ax + bb.x, 0.f);
    out.y = fmaxf(ay + bb.y, 0.f);
    out.z = fmaxf(az + bb.z, 0.f);
    out.w = fmaxf(aw + bb.w, 0.f);
    reinterpret_cast<float4*>(g_g1)[(long long)node * 32 + lane] = out;
}

// ---------------- GEMM2: h2 = g1(Mx128) @ W2(128x16), reg-blocked ----------
#define GP 68    // s_g row pad (floats)
#define WP 132   // s_wt row pad (floats)
__global__ void __launch_bounds__(128) k_gemm2(const float* __restrict__ W2, int M) {
    __shared__ float s_g[128][GP];   // [node][k-chunk 64]
    __shared__ float s_wt[16][WP];   // [col][k 0..127] transposed W2
    const int tid  = threadIdx.x;
    const int ng   = tid >> 2;       // node group 0..31 (4 nodes each)
    const int cg   = tid & 3;        // col group 0..3 (4 cols each)
    const int node0 = blockIdx.x * 128;

    for (int idx = tid; idx < 2048; idx += 128) {
        int k = idx >> 4, j = idx & 15;
        s_wt[j][k] = W2[idx];
    }

    float acc[4][4];
    #pragma unroll
    for (int m = 0; m < 4; m++)
        #pragma unroll
        for (int j = 0; j < 4; j++) acc[m][j] = 0.f;

    #pragma unroll
    for (int kc = 0; kc < 2; kc++) {
        const int k0 = kc * 64;
        __syncthreads();
        #pragma unroll
        for (int i = 0; i < 16; i++) {
            int idx = i * 128 + tid;
            int nd = idx >> 4, kq = idx & 15;
            float4 v = make_float4(0.f, 0.f, 0.f, 0.f);
            if (node0 + nd < M)
                v = *reinterpret_cast<const float4*>(&g_g1[(long long)(node0 + nd) * NHID + k0 + kq * 4]);
            *reinterpret_cast<float4*>(&s_g[nd][kq * 4]) = v;
        }
        __syncthreads();
        #pragma unroll
        for (int kq = 0; kq < 16; kq++) {
            float4 a[4], b[4];
            #pragma unroll
            for (int m = 0; m < 4; m++)
                a[m] = *reinterpret_cast<const float4*>(&s_g[ng * 4 + m][kq * 4]);
            #pragma unroll
            for (int j = 0; j < 4; j++)
                b[j] = *reinterpret_cast<const float4*>(&s_wt[cg * 4 + j][k0 + kq * 4]);
            #pragma unroll
            for (int m = 0; m < 4; m++)
                #pragma unroll
                for (int j = 0; j < 4; j++)
                    acc[m][j] += a[m].x * b[j].x + a[m].y * b[j].y
                               + a[m].z * b[j].z + a[m].w * b[j].w;
        }
    }

    #pragma unroll
    for (int m = 0; m < 4; m++) {
        int nd = node0 + ng * 4 + m;
        if (nd < M)
            *reinterpret_cast<float4*>(&g_h2[(long long)nd * 16 + cg * 4]) =
                make_float4(acc[m][0], acc[m][1], acc[m][2], acc[m][3]);
    }
}

// ---------------- agg2: out = Ahat @ h2 + b2, 16 threads per node ----------
__global__ void __launch_bounds__(256) k_agg2(const float* __restrict__ b2,
                                              float* __restrict__ out, int n) {
    int gtid = blockIdx.x * blockDim.x + threadIdx.x;
    int node = gtid >> 4;
    int lane = threadIdx.x & 15;
    if (node >= n) return;
    float dv = g_dinv[node];
    float acc = g_h2[(long long)node * 16 + lane] * dv * dv;
    int p = g_off[node], end = g_off[node + 1];
    for (; p + 3 < end; p += 4) {
        int2 e0 = g_edge[p],     e1 = g_edge[p + 1];
        int2 e2 = g_edge[p + 2], e3 = g_edge[p + 3];
        acc += g_h2[(long long)e0.x * 16 + lane] * __int_as_float(e0.y)
             + g_h2[(long long)e1.x * 16 + lane] * __int_as_float(e1.y)
             + g_h2[(long long)e2.x * 16 + lane] * __int_as_float(e2.y)
             + g_h2[(long long)e3.x * 16 + lane] * __int_as_float(e3.y);
    }
    for (; p < end; p++) {
        int2 e0 = g_edge[p];
        acc += g_h2[(long long)e0.x * 16 + lane] * __int_as_float(e0.y);
    }
    out[(long long)node * 16 + lane] = acc + b2[lane];
}

// ---------------- launch ----------------------------------------------------
extern "C" void kernel_launch(void* const* d_in, const int* in_sizes, int n_in,
                              void* d_out, int out_size) {
    const float* x  = (const float*)d_in[0];
    const void*  ei = d_in[1];
    const float* W1 = (const float*)d_in[2];
    const float* b1 = (const float*)d_in[3];
    const float* W2 = (const float*)d_in[4];
    const float* b2 = (const float*)d_in[5];
    float* out = (float*)d_out;

    int n = in_sizes[0] / NFEAT;
    int E = in_sizes[1] / 2;

    int gN = (n + 255) / 256;
    int gE = (E + 255) / 256;
    int nb = (n + SCANB - 1) / SCANB;

    const bool fork = g_hx.ok;
    cudaStream_t sb = fork ? g_hx.s2 : (cudaStream_t)0;

    // fork: graph-build chain runs concurrently with GEMM1
    if (fork) {
        cudaEventRecord(g_hx.evA, 0);
        cudaStreamWaitEvent(g_hx.s2, g_hx.evA, 0);
    }
    k_init<<<gN, 256, 0, sb>>>((const int*)ei, n, E);
    k_count<<<gE, 256, 0, sb>>>(ei, E);
    k_scan_block<<<nb, SCANB, 0, sb>>>(n);
    k_scan_tops<<<1, 128, 0, sb>>>(nb, n);
    k_scan_add<<<nb, SCANB, 0, sb>>>(n);
    k_scatter<<<gE, 256, 0, sb>>>(ei, E);
    if (fork) cudaEventRecord(g_hx.evB, g_hx.s2);

    k_gemm1<<<(n + 127) / 128, 256>>>(x, W1, n);

    if (fork) cudaStreamWaitEvent(0, g_hx.evB, 0);  // join before agg1

    k_agg1<<<(n * 32 + 255) / 256, 256>>>(b1, n);
    k_gemm2<<<(n + 127) / 128, 128>>>(W2, n);
    k_agg2<<<(n * 16 + 255) / 256, 256>>>(b2, out, n);
}

// round 8
// speedup vs baseline: 1.9835x; 1.0610x over previous
#include <cuda_runtime.h>
#include <cuda_fp16.h>
#include <cstdint>

#define NFEAT   256
#define NHID    128
#define NCLS    16
#define MAXN    100000
#define MAXE    1600000
#define SCANB   1024
#define MAXBLK  128

// ---------------- scratch (device globals; no allocation allowed) ----------
__device__ int    g_cnt[MAXN];
__device__ int    g_cur[MAXN];
__device__ int    g_off[MAXN + 1];
__device__ int    g_bsum[MAXBLK];
__device__ int    g_boff[MAXBLK];
__device__ float  g_dinv[MAXN];
__device__ int2   g_edge[MAXE];             // x = src node, y = weight bits
__device__ __half g_h1h[(size_t)MAXN * NHID];   // h1 in fp16 (gather-friendly)
__device__ float  g_g1[(size_t)MAXN * NHID];    // layer-2 input stays fp32
__device__ __half g_h2h[(size_t)MAXN * NCLS];   // h2 in fp16
__device__ int    g_is64;

// ---------------- static host context: fork-join stream + events -----------
struct HxCtx {
    cudaStream_t s2;
    cudaEvent_t  evA, evB;
    bool ok;
    HxCtx() : ok(false) {
        if (cudaStreamCreateWithFlags(&s2, cudaStreamNonBlocking) != cudaSuccess) return;
        if (cudaEventCreateWithFlags(&evA, cudaEventDisableTiming) != cudaSuccess) return;
        if (cudaEventCreateWithFlags(&evB, cudaEventDisableTiming) != cudaSuccess) return;
        ok = true;
    }
};
static HxCtx g_hx;

// ---------------- index fetch (runtime int32/int64 dispatch) ---------------
__device__ __forceinline__ int edge_idx(const void* ei, long long pos, int is64) {
    if (is64) return (int)((const long long*)ei)[pos];
    return ((const int*)ei)[pos];
}

// ---------------- init: zero counters + detect index dtype -----------------
__global__ void k_init(const int* __restrict__ ei32, int n, int E) {
    int i = blockIdx.x * blockDim.x + threadIdx.x;
    if (i < n) g_cnt[i] = 0;
    if (blockIdx.x == 0) {
        int samples = 4096;
        if (samples > E / 2) samples = E / 2;
        int nz = 0;
        for (int s = threadIdx.x; s < samples; s += blockDim.x)
            if (ei32[2 * s + 1] != 0) nz = 1;
        nz = __syncthreads_or(nz);
        if (threadIdx.x == 0) g_is64 = nz ? 0 : 1;
    }
}

// ---------------- degree count ---------------------------------------------
__global__ void k_count(const void* __restrict__ ei, int E) {
    int e = blockIdx.x * blockDim.x + threadIdx.x;
    if (e >= E) return;
    int c = edge_idx(ei, (long long)E + e, g_is64);
    atomicAdd(&g_cnt[c], 1);
}

// ---------------- scan phase 1: per-block scan + dinv -----------------------
__global__ void __launch_bounds__(SCANB) k_scan_block(int n) {
    __shared__ int warp_sums[32];
    int tid = threadIdx.x, lane = tid & 31, wid = tid >> 5;
    int i = blockIdx.x * SCANB + tid;
    int v = (i < n) ? g_cnt[i] : 0;
    if (i < n) g_dinv[i] = rsqrtf((float)v + 1.0f); // +1 = self loop
    int x = v;
    #pragma unroll
    for (int d = 1; d < 32; d <<= 1) {
        int y = __shfl_up_sync(0xffffffffu, x, d);
        if (lane >= d) x += y;
    }
    if (lane == 31) warp_sums[wid] = x;
    __syncthreads();
    if (wid == 0) {
        int s = warp_sums[lane];
        #pragma unroll
        for (int d = 1; d < 32; d <<= 1) {
            int y = __shfl_up_sync(0xffffffffu, s, d);
            if (lane >= d) s += y;
        }
        warp_sums[lane] = s;
    }
    __syncthreads();
    int excl = x - v + (wid ? warp_sums[wid - 1] : 0);
    if (i < n) g_off[i] = excl;
    if (tid == SCANB - 1) g_bsum[blockIdx.x] = excl + v;
}

// ---------------- scan phase 2 ----------------------------------------------
__global__ void k_scan_tops(int nb, int n) {
    __shared__ int warp_sums[32];
    int tid = threadIdx.x, lane = tid & 31, wid = tid >> 5;
    int v = (tid < nb) ? g_bsum[tid] : 0;
    int x = v;
    #pragma unroll
    for (int d = 1; d < 32; d <<= 1) {
        int y = __shfl_up_sync(0xffffffffu, x, d);
        if (lane >= d) x += y;
    }
    if (lane == 31) warp_sums[wid] = x;
    __syncthreads();
    if (wid == 0) {
        int s = warp_sums[lane];
        #pragma unroll
        for (int d = 1; d < 32; d <<= 1) {
            int y = __shfl_up_sync(0xffffffffu, s, d);
            if (lane >= d) s += y;
        }
        warp_sums[lane] = s;
    }
    __syncthreads();
    int excl = x - v + (wid ? warp_sums[wid - 1] : 0);
    if (tid < nb) g_boff[tid] = excl;
    if (tid == nb - 1) g_off[n] = excl + v;
}

// ---------------- scan phase 3 ----------------------------------------------
__global__ void __launch_bounds__(SCANB) k_scan_add(int n) {
    int i = blockIdx.x * SCANB + threadIdx.x;
    if (i < n) {
        int v = g_off[i] + g_boff[blockIdx.x];
        g_off[i] = v;
        g_cur[i] = v;
    }
}

// ---------------- scatter edges into CSC (interleaved src+w) ---------------
__global__ void k_scatter(const void* __restrict__ ei, int E) {
    int e = blockIdx.x * blockDim.x + threadIdx.x;
    if (e >= E) return;
    int is64 = g_is64;
    int r = edge_idx(ei, e, is64);
    int c = edge_idx(ei, (long long)E + e, is64);
    int p = atomicAdd(&g_cur[c], 1);
    g_edge[p] = make_int2(r, __float_as_int(g_dinv[r] * g_dinv[c]));
}

// ---------------- tf32 helpers ----------------------------------------------
__device__ __forceinline__ uint32_t f2tf32(float f) {
    uint32_t u;
    asm("cvt.rna.tf32.f32 %0, %1;" : "=r"(u) : "f"(f));
    return u;
}
__device__ __forceinline__ void mma_tf32(float* d, const uint32_t* a, uint32_t b0, uint32_t b1) {
    asm("mma.sync.aligned.m16n8k8.row.col.f32.tf32.tf32.f32 "
        "{%0,%1,%2,%3}, {%4,%5,%6,%7}, {%8,%9}, {%0,%1,%2,%3};"
        : "+f"(d[0]), "+f"(d[1]), "+f"(d[2]), "+f"(d[3])
        : "r"(a[0]), "r"(a[1]), "r"(a[2]), "r"(a[3]), "r"(b0), "r"(b1));
}

// ---------------- GEMM1 (mma.sync tf32): h1 = x(Mx256) @ W1(256x128) -------
#define AP 20   // As row pad
#define BP 136  // Bs row pad
__global__ void __launch_bounds__(256) k_gemm1(const float* __restrict__ A,
                                               const float* __restrict__ B,
                                               int M) {
    __shared__ uint32_t As[128][AP];   // [row][k0..15] tf32 bits
    __shared__ uint32_t Bs[16][BP];    // [k][col0..127] tf32 bits
    const int tid    = threadIdx.x;
    const int lane   = tid & 31;
    const int wid    = tid >> 5;
    const int warp_m = (wid & 3) * 32;   // 4 warps along M
    const int warp_n = (wid >> 2) * 64;  // 2 warps along N
    const int brow   = blockIdx.x * 128;

    float acc[2][8][4];
    #pragma unroll
    for (int mt = 0; mt < 2; mt++)
        #pragma unroll
        for (int nt = 0; nt < 8; nt++)
            #pragma unroll
            for (int q = 0; q < 4; q++) acc[mt][nt][q] = 0.f;

    const int a_row = tid >> 1;          // 0..127
    const int a_kq  = (tid & 1) * 8;     // 0 or 8
    const int b_k   = tid >> 4;          // 0..15
    const int b_c   = (tid & 15) * 8;    // 0..120
    const int r4    = lane >> 2;         // 0..7
    const int c4    = lane & 3;          // 0..3

    for (int k0 = 0; k0 < NFEAT; k0 += 16) {
        // stage A (convert to tf32)
        int gr = brow + a_row;
        float4 v0 = make_float4(0.f, 0.f, 0.f, 0.f);
        float4 v1 = make_float4(0.f, 0.f, 0.f, 0.f);
        if (gr < M) {
            v0 = *reinterpret_cast<const float4*>(&A[(long long)gr * NFEAT + k0 + a_kq]);
            v1 = *reinterpret_cast<const float4*>(&A[(long long)gr * NFEAT + k0 + a_kq + 4]);
        }
        As[a_row][a_kq + 0] = f2tf32(v0.x);
        As[a_row][a_kq + 1] = f2tf32(v0.y);
        As[a_row][a_kq + 2] = f2tf32(v0.z);
        As[a_row][a_kq + 3] = f2tf32(v0.w);
        As[a_row][a_kq + 4] = f2tf32(v1.x);
        As[a_row][a_kq + 5] = f2tf32(v1.y);
        As[a_row][a_kq + 6] = f2tf32(v1.z);
        As[a_row][a_kq + 7] = f2tf32(v1.w);
        // stage B (convert to tf32)
        float4 w0 = *reinterpret_cast<const float4*>(&B[(k0 + b_k) * NHID + b_c]);
        float4 w1 = *reinterpret_cast<const float4*>(&B[(k0 + b_k) * NHID + b_c + 4]);
        Bs[b_k][b_c + 0] = f2tf32(w0.x);
        Bs[b_k][b_c + 1] = f2tf32(w0.y);
        Bs[b_k][b_c + 2] = f2tf32(w0.z);
        Bs[b_k][b_c + 3] = f2tf32(w0.w);
        Bs[b_k][b_c + 4] = f2tf32(w1.x);
        Bs[b_k][b_c + 5] = f2tf32(w1.y);
        Bs[b_k][b_c + 6] = f2tf32(w1.z);
        Bs[b_k][b_c + 7] = f2tf32(w1.w);
        __syncthreads();

        #pragma unroll
        for (int kc = 0; kc < 2; kc++) {
            const int kb = kc * 8;
            uint32_t afr[2][4];
            #pragma unroll
            for (int mt = 0; mt < 2; mt++) {
                int row = warp_m + mt * 16 + r4;
                afr[mt][0] = As[row][kb + c4];
                afr[mt][1] = As[row + 8][kb + c4];
                afr[mt][2] = As[row][kb + c4 + 4];
                afr[mt][3] = As[row + 8][kb + c4 + 4];
            }
            #pragma unroll
            for (int nt = 0; nt < 8; nt++) {
                int col = warp_n + nt * 8 + r4;
                uint32_t b0 = Bs[kb + c4][col];
                uint32_t b1 = Bs[kb + c4 + 4][col];
                mma_tf32(acc[0][nt], afr[0], b0, b1);
                mma_tf32(acc[1][nt], afr[1], b0, b1);
            }
        }
        __syncthreads();
    }

    // epilogue: write h1 as fp16 (half2 per register pair)
    #pragma unroll
    for (int mt = 0; mt < 2; mt++) {
        int row0 = brow + warp_m + mt * 16 + r4;
        #pragma unroll
        for (int nt = 0; nt < 8; nt++) {
            int col = warp_n + nt * 8 + 2 * c4;
            if (row0 < M)
                *reinterpret_cast<__half2*>(&g_h1h[(long long)row0 * NHID + col]) =
                    __floats2half2_rn(acc[mt][nt][0], acc[mt][nt][1]);
            if (row0 + 8 < M)
                *reinterpret_cast<__half2*>(&g_h1h[(long long)(row0 + 8) * NHID + col]) =
                    __floats2half2_rn(acc[mt][nt][2], acc[mt][nt][3]);
        }
    }
}

// ---------------- agg1: g1 = relu(Ahat @ h1 + b1), warp per node, fp16 gather
__global__ void __launch_bounds__(256) k_agg1(const float* __restrict__ b1, int n) {
    int gtid = blockIdx.x * blockDim.x + threadIdx.x;
    int node = gtid >> 5;
    int lane = threadIdx.x & 31;
    if (node >= n) return;
    const uint2* h1v = reinterpret_cast<const uint2*>(g_h1h); // 8B = 4 halves per lane
    float dv = g_dinv[node];
    float sw = dv * dv;

    uint2 hu = h1v[(long long)node * 32 + lane];
    float2 p0 = __half22float2(*reinterpret_cast<__half2*>(&hu.x));
    float2 p1 = __half22float2(*reinterpret_cast<__half2*>(&hu.y));
    float ax = p0.x * sw, ay = p0.y * sw, az = p1.x * sw, aw = p1.y * sw;

    int p = g_off[node], end = g_off[node + 1];
    for (; p + 3 < end; p += 4) {
        int2 e0 = g_edge[p],     e1 = g_edge[p + 1];
        int2 e2 = g_edge[p + 2], e3 = g_edge[p + 3];
        float w0 = __int_as_float(e0.y), w1 = __int_as_float(e1.y);
        float w2 = __int_as_float(e2.y), w3 = __int_as_float(e3.y);
        uint2 u0 = h1v[(long long)e0.x * 32 + lane];
        uint2 u1 = h1v[(long long)e1.x * 32 + lane];
        uint2 u2 = h1v[(long long)e2.x * 32 + lane];
        uint2 u3 = h1v[(long long)e3.x * 32 + lane];
        float2 a0 = __half22float2(*reinterpret_cast<__half2*>(&u0.x));
        float2 b0 = __half22float2(*reinterpret_cast<__half2*>(&u0.y));
        float2 a1 = __half22float2(*reinterpret_cast<__half2*>(&u1.x));
        float2 b1v = __half22float2(*reinterpret_cast<__half2*>(&u1.y));
        float2 a2 = __half22float2(*reinterpret_cast<__half2*>(&u2.x));
        float2 b2v = __half22float2(*reinterpret_cast<__half2*>(&u2.y));
        float2 a3 = __half22float2(*reinterpret_cast<__half2*>(&u3.x));
        float2 b3v = __half22float2(*reinterpret_cast<__half2*>(&u3.y));
        ax += a0.x * w0 + a1.x * w1 + a2.x * w2 + a3.x * w3;
        ay += a0.y * w0 + a1.y * w1 + a2.y * w2 + a3.y * w3;
        az += b0.x * w0 + b1v.x * w1 + b2v.x * w2 + b3v.x * w3;
        aw += b0.y * w0 + b1v.y * w1 + b2v.y * w2 + b3v.y * w3;
    }
    for (; p < end; p++) {
        int2 e0 = g_edge[p];
        float w0 = __int_as_float(e0.y);
        uint2 u0 = h1v[(long long)e0.x * 32 + lane];
        float2 a0 = __half22float2(*reinterpret_cast<__half2*>(&u0.x));
        float2 b0 = __half22float2(*reinterpret_cast<__half2*>(&u0.y));
        ax += a0.x * w0; ay += a0.y * w0; az += b0.x * w0; aw += b0.y * w0;
    }
    float4 bb = reinterpret_cast<const float4*>(b1)[lane];
    float4 out;
    out.x = fmaxf(ax + bb.x, 0.f);
    out.y = fmaxf(ay + bb.y, 0.f);
    out.z = fmaxf(az + bb.z, 0.f);
    out.w = fmaxf(aw + bb.w, 0.f);
    reinterpret_cast<float4*>(g_g1)[(long long)node * 32 + lane] = out;
}

// ---------------- GEMM2: h2 = g1(Mx128) @ W2(128x16), reg-blocked, fp16 out
#define GP 68    // s_g row pad (floats)
#define WP 132   // s_wt row pad (floats)
__global__ void __launch_bounds__(128) k_gemm2(const float* __restrict__ W2, int M) {
    __shared__ float s_g[128][GP];   // [node][k-chunk 64]
    __shared__ float s_wt[16][WP];   // [col][k 0..127] transposed W2
    const int tid  = threadIdx.x;
    const int ng   = tid >> 2;       // node group 0..31 (4 nodes each)
    const int cg   = tid & 3;        // col group 0..3 (4 cols each)
    const int node0 = blockIdx.x * 128;

    for (int idx = tid; idx < 2048; idx += 128) {
        int k = idx >> 4, j = idx & 15;
        s_wt[j][k] = W2[idx];
    }

    float acc[4][4];
    #pragma unroll
    for (int m = 0; m < 4; m++)
        #pragma unroll
        for (int j = 0; j < 4; j++) acc[m][j] = 0.f;

    #pragma unroll
    for (int kc = 0; kc < 2; kc++) {
        const int k0 = kc * 64;
        __syncthreads();
        #pragma unroll
        for (int i = 0; i < 16; i++) {
            int idx = i * 128 + tid;
            int nd = idx >> 4, kq = idx & 15;
            float4 v = make_float4(0.f, 0.f, 0.f, 0.f);
            if (node0 + nd < M)
                v = *reinterpret_cast<const float4*>(&g_g1[(long long)(node0 + nd) * NHID + k0 + kq * 4]);
            *reinterpret_cast<float4*>(&s_g[nd][kq * 4]) = v;
        }
        __syncthreads();
        #pragma unroll
        for (int kq = 0; kq < 16; kq++) {
            float4 a[4], b[4];
            #pragma unroll
            for (int m = 0; m < 4; m++)
                a[m] = *reinterpret_cast<const float4*>(&s_g[ng * 4 + m][kq * 4]);
            #pragma unroll
            for (int j = 0; j < 4; j++)
                b[j] = *reinterpret_cast<const float4*>(&s_wt[cg * 4 + j][k0 + kq * 4]);
            #pragma unroll
            for (int m = 0; m < 4; m++)
                #pragma unroll
                for (int j = 0; j < 4; j++)
                    acc[m][j] += a[m].x * b[j].x + a[m].y * b[j].y
                               + a[m].z * b[j].z + a[m].w * b[j].w;
        }
    }

    #pragma unroll
    for (int m = 0; m < 4; m++) {
        int nd = node0 + ng * 4 + m;
        if (nd < M) {
            __half2 q0 = __floats2half2_rn(acc[m][0], acc[m][1]);
            __half2 q1 = __floats2half2_rn(acc[m][2], acc[m][3]);
            *reinterpret_cast<__half2*>(&g_h2h[(long long)nd * 16 + cg * 4])     = q0;
            *reinterpret_cast<__half2*>(&g_h2h[(long long)nd * 16 + cg * 4 + 2]) = q1;
        }
    }
}

// ---------------- agg2: out = Ahat @ h2 + b2, 16 threads per node, fp16 ----
__global__ void __launch_bounds__(256) k_agg2(const float* __restrict__ b2,
                                              float* __restrict__ out, int n) {
    int gtid = blockIdx.x * blockDim.x + threadIdx.x;
    int node = gtid >> 4;
    int lane = threadIdx.x & 15;
    if (node >= n) return;
    float dv = g_dinv[node];
    float acc = __half2float(g_h2h[(long long)node * 16 + lane]) * dv * dv;
    int p = g_off[node], end = g_off[node + 1];
    for (; p + 3 < end; p += 4) {
        int2 e0 = g_edge[p],     e1 = g_edge[p + 1];
        int2 e2 = g_edge[p + 2], e3 = g_edge[p + 3];
        acc += __half2float(g_h2h[(long long)e0.x * 16 + lane]) * __int_as_float(e0.y)
             + __half2float(g_h2h[(long long)e1.x * 16 + lane]) * __int_as_float(e1.y)
             + __half2float(g_h2h[(long long)e2.x * 16 + lane]) * __int_as_float(e2.y)
             + __half2float(g_h2h[(long long)e3.x * 16 + lane]) * __int_as_float(e3.y);
    }
    for (; p < end; p++) {
        int2 e0 = g_edge[p];
        acc += __half2float(g_h2h[(long long)e0.x * 16 + lane]) * __int_as_float(e0.y);
    }
    out[(long long)node * 16 + lane] = acc + b2[lane];
}

// ---------------- launch ----------------------------------------------------
extern "C" void kernel_launch(void* const* d_in, const int* in_sizes, int n_in,
                              void* d_out, int out_size) {
    const float* x  = (const float*)d_in[0];
    const void*  ei = d_in[1];
    const float* W1 = (const float*)d_in[2];
    const float* b1 = (const float*)d_in[3];
    const float* W2 = (const float*)d_in[4];
    const float* b2 = (const float*)d_in[5];
    float* out = (float*)d_out;

    int n = in_sizes[0] / NFEAT;
    int E = in_sizes[1] / 2;

    int gN = (n + 255) / 256;
    int gE = (E + 255) / 256;
    int nb = (n + SCANB - 1) / SCANB;

    const bool fork = g_hx.ok;
    cudaStream_t sb = fork ? g_hx.s2 : (cudaStream_t)0;

    // fork: graph-build chain runs concurrently with GEMM1
    if (fork) {
        cudaEventRecord(g_hx.evA, 0);
        cudaStreamWaitEvent(g_hx.s2, g_hx.evA, 0);
    }
    k_init<<<gN, 256, 0, sb>>>((const int*)ei, n, E);
    k_count<<<gE, 256, 0, sb>>>(ei, E);
    k_scan_block<<<nb, SCANB, 0, sb>>>(n);
    k_scan_tops<<<1, 128, 0, sb>>>(nb, n);
    k_scan_add<<<nb, SCANB, 0, sb>>>(n);
    k_scatter<<<gE, 256, 0, sb>>>(ei, E);
    if (fork) cudaEventRecord(g_hx.evB, g_hx.s2);

    k_gemm1<<<(n + 127) / 128, 256>>>(x, W1, n);

    if (fork) cudaStreamWaitEvent(0, g_hx.evB, 0);  // join before agg1

    k_agg1<<<(n * 32 + 255) / 256, 256>>>(b1, n);
    k_gemm2<<<(n + 127) / 128, 128>>>(W2, n);
    k_agg2<<<(n * 16 + 255) / 256, 256>>>(b2, out, n);
}

// round 9
// speedup vs baseline: 1.9857x; 1.0011x over previous
#include <cuda_runtime.h>
#include <cuda_fp16.h>
#include <cstdint>

#define NFEAT   256
#define NHID    128
#define NCLS    16
#define MAXN    100000
#define MAXE    1600000
#define SCANB   1024
#define MAXBLK  128

// ---------------- scratch (device globals; no allocation allowed) ----------
__device__ int    g_cnt[MAXN];
__device__ int    g_cur[MAXN];
__device__ int    g_off[MAXN + 1];
__device__ int    g_bsum[MAXBLK];
__device__ int    g_boff[MAXBLK];
__device__ float  g_dinv[MAXN];
__device__ int2   g_edge[MAXE];             // x = src node, y = weight bits
__device__ __half g_h1h[(size_t)MAXN * NHID];   // h1 in fp16 (gather-friendly)
__device__ float  g_g1[(size_t)MAXN * NHID];    // layer-2 input stays fp32
__device__ __half g_h2h[(size_t)MAXN * NCLS];   // h2 in fp16
__device__ int    g_is64;

// ---------------- static host context: fork-join stream + events -----------
struct HxCtx {
    cudaStream_t s2;
    cudaEvent_t  evA, evB;
    bool ok;
    HxCtx() : ok(false) {
        if (cudaStreamCreateWithFlags(&s2, cudaStreamNonBlocking) != cudaSuccess) return;
        if (cudaEventCreateWithFlags(&evA, cudaEventDisableTiming) != cudaSuccess) return;
        if (cudaEventCreateWithFlags(&evB, cudaEventDisableTiming) != cudaSuccess) return;
        ok = true;
    }
};
static HxCtx g_hx;

// ---------------- index fetch (runtime int32/int64 dispatch) ---------------
__device__ __forceinline__ int edge_idx(const void* ei, long long pos, int is64) {
    if (is64) return (int)((const long long*)ei)[pos];
    return ((const int*)ei)[pos];
}

// ---------------- init: zero counters + detect index dtype -----------------
__global__ void k_init(const int* __restrict__ ei32, int n, int E) {
    int i = blockIdx.x * blockDim.x + threadIdx.x;
    if (i < n) g_cnt[i] = 0;
    if (blockIdx.x == 0) {
        int samples = 4096;
        if (samples > E / 2) samples = E / 2;
        int nz = 0;
        for (int s = threadIdx.x; s < samples; s += blockDim.x)
            if (ei32[2 * s + 1] != 0) nz = 1;
        nz = __syncthreads_or(nz);
        if (threadIdx.x == 0) g_is64 = nz ? 0 : 1;
    }
}

// ---------------- degree count ---------------------------------------------
__global__ void k_count(const void* __restrict__ ei, int E) {
    int e = blockIdx.x * blockDim.x + threadIdx.x;
    if (e >= E) return;
    int c = edge_idx(ei, (long long)E + e, g_is64);
    atomicAdd(&g_cnt[c], 1);
}

// ---------------- scan phase 1: per-block scan + dinv -----------------------
__global__ void __launch_bounds__(SCANB) k_scan_block(int n) {
    __shared__ int warp_sums[32];
    int tid = threadIdx.x, lane = tid & 31, wid = tid >> 5;
    int i = blockIdx.x * SCANB + tid;
    int v = (i < n) ? g_cnt[i] : 0;
    if (i < n) g_dinv[i] = rsqrtf((float)v + 1.0f); // +1 = self loop
    int x = v;
    #pragma unroll
    for (int d = 1; d < 32; d <<= 1) {
        int y = __shfl_up_sync(0xffffffffu, x, d);
        if (lane >= d) x += y;
    }
    if (lane == 31) warp_sums[wid] = x;
    __syncthreads();
    if (wid == 0) {
        int s = warp_sums[lane];
        #pragma unroll
        for (int d = 1; d < 32; d <<= 1) {
            int y = __shfl_up_sync(0xffffffffu, s, d);
            if (lane >= d) s += y;
        }
        warp_sums[lane] = s;
    }
    __syncthreads();
    int excl = x - v + (wid ? warp_sums[wid - 1] : 0);
    if (i < n) g_off[i] = excl;
    if (tid == SCANB - 1) g_bsum[blockIdx.x] = excl + v;
}

// ---------------- scan phase 2 ----------------------------------------------
__global__ void k_scan_tops(int nb, int n) {
    __shared__ int warp_sums[32];
    int tid = threadIdx.x, lane = tid & 31, wid = tid >> 5;
    int v = (tid < nb) ? g_bsum[tid] : 0;
    int x = v;
    #pragma unroll
    for (int d = 1; d < 32; d <<= 1) {
        int y = __shfl_up_sync(0xffffffffu, x, d);
        if (lane >= d) x += y;
    }
    if (lane == 31) warp_sums[wid] = x;
    __syncthreads();
    if (wid == 0) {
        int s = warp_sums[lane];
        #pragma unroll
        for (int d = 1; d < 32; d <<= 1) {
            int y = __shfl_up_sync(0xffffffffu, s, d);
            if (lane >= d) s += y;
        }
        warp_sums[lane] = s;
    }
    __syncthreads();
    int excl = x - v + (wid ? warp_sums[wid - 1] : 0);
    if (tid < nb) g_boff[tid] = excl;
    if (tid == nb - 1) g_off[n] = excl + v;
}

// ---------------- scan phase 3 ----------------------------------------------
__global__ void __launch_bounds__(SCANB) k_scan_add(int n) {
    int i = blockIdx.x * SCANB + threadIdx.x;
    if (i < n) {
        int v = g_off[i] + g_boff[blockIdx.x];
        g_off[i] = v;
        g_cur[i] = v;
    }
}

// ---------------- scatter edges into CSC (interleaved src+w) ---------------
__global__ void k_scatter(const void* __restrict__ ei, int E) {
    int e = blockIdx.x * blockDim.x + threadIdx.x;
    if (e >= E) return;
    int is64 = g_is64;
    int r = edge_idx(ei, e, is64);
    int c = edge_idx(ei, (long long)E + e, is64);
    int p = atomicAdd(&g_cur[c], 1);
    g_edge[p] = make_int2(r, __float_as_int(g_dinv[r] * g_dinv[c]));
}

// ---------------- fp16 mma helper -------------------------------------------
__device__ __forceinline__ void mma_f16(float* d, const uint32_t* a, uint32_t b0, uint32_t b1) {
    asm("mma.sync.aligned.m16n8k16.row.col.f32.f16.f16.f32 "
        "{%0,%1,%2,%3}, {%4,%5,%6,%7}, {%8,%9}, {%0,%1,%2,%3};"
        : "+f"(d[0]), "+f"(d[1]), "+f"(d[2]), "+f"(d[3])
        : "r"(a[0]), "r"(a[1]), "r"(a[2]), "r"(a[3]), "r"(b0), "r"(b1));
}
__device__ __forceinline__ uint32_t pack_h2(float lo, float hi) {
    __half2 h = __floats2half2_rn(lo, hi);
    return *reinterpret_cast<uint32_t*>(&h);
}

// ---------------- GEMM1 (mma.sync fp16): h1 = x(Mx256) @ W1(256x128) -------
#define AP2 12   // padded row length (uints) for both smem tiles
__global__ void __launch_bounds__(256) k_gemm1(const float* __restrict__ A,
                                               const float* __restrict__ B,
                                               int M) {
    __shared__ uint32_t As2[128][AP2];  // A halves: [row][k-pair 0..7]
    __shared__ uint32_t Bs2[128][AP2];  // B halves col-major: [col][k-pair 0..7]
    const int tid    = threadIdx.x;
    const int lane   = tid & 31;
    const int wid    = tid >> 5;
    const int warp_m = (wid & 3) * 32;   // 4 warps along M
    const int warp_n = (wid >> 2) * 64;  // 2 warps along N
    const int brow   = blockIdx.x * 128;

    float acc[2][8][4];
    #pragma unroll
    for (int mt = 0; mt < 2; mt++)
        #pragma unroll
        for (int nt = 0; nt < 8; nt++)
            #pragma unroll
            for (int q = 0; q < 4; q++) acc[mt][nt][q] = 0.f;

    const int a_row = tid >> 1;          // 0..127
    const int a_kq  = (tid & 1) * 4;     // uint index: 0 or 4 (half index 0/8)
    const int r4    = lane >> 2;         // 0..7
    const int c4    = lane & 3;          // 0..3

    for (int k0 = 0; k0 < NFEAT; k0 += 16) {
        // stage A: 8 fp32 -> 4 packed half2
        int gr = brow + a_row;
        float4 v0 = make_float4(0.f, 0.f, 0.f, 0.f);
        float4 v1 = make_float4(0.f, 0.f, 0.f, 0.f);
        if (gr < M) {
            v0 = *reinterpret_cast<const float4*>(&A[(long long)gr * NFEAT + k0 + a_kq * 2]);
            v1 = *reinterpret_cast<const float4*>(&A[(long long)gr * NFEAT + k0 + a_kq * 2 + 4]);
        }
        uint4 au;
        au.x = pack_h2(v0.x, v0.y);
        au.y = pack_h2(v0.z, v0.w);
        au.z = pack_h2(v1.x, v1.y);
        au.w = pack_h2(v1.z, v1.w);
        *reinterpret_cast<uint4*>(&As2[a_row][a_kq]) = au;

        // stage B transposed: Bs2[n][kk] = (W1[k0+2kk][n], W1[k0+2kk+1][n])
        #pragma unroll
        for (int i = 0; i < 4; i++) {
            int idx = i * 256 + tid;       // 0..1023
            int nn  = idx & 127;
            int kk  = idx >> 7;            // 0..7
            float f0 = B[(k0 + 2 * kk) * NHID + nn];
            float f1 = B[(k0 + 2 * kk + 1) * NHID + nn];
            Bs2[nn][kk] = pack_h2(f0, f1);
        }
        __syncthreads();

        uint32_t afr[2][4];
        #pragma unroll
        for (int mt = 0; mt < 2; mt++) {
            int row = warp_m + mt * 16 + r4;
            afr[mt][0] = As2[row][c4];
            afr[mt][1] = As2[row + 8][c4];
            afr[mt][2] = As2[row][c4 + 4];
            afr[mt][3] = As2[row + 8][c4 + 4];
        }
        #pragma unroll
        for (int nt = 0; nt < 8; nt++) {
            int col = warp_n + nt * 8 + r4;
            uint32_t b0 = Bs2[col][c4];
            uint32_t b1 = Bs2[col][c4 + 4];
            mma_f16(acc[0][nt], afr[0], b0, b1);
            mma_f16(acc[1][nt], afr[1], b0, b1);
        }
        __syncthreads();
    }

    // epilogue: write h1 as fp16 (half2 per register pair)
    #pragma unroll
    for (int mt = 0; mt < 2; mt++) {
        int row0 = brow + warp_m + mt * 16 + r4;
        #pragma unroll
        for (int nt = 0; nt < 8; nt++) {
            int col = warp_n + nt * 8 + 2 * c4;
            if (row0 < M)
                *reinterpret_cast<__half2*>(&g_h1h[(long long)row0 * NHID + col]) =
                    __floats2half2_rn(acc[mt][nt][0], acc[mt][nt][1]);
            if (row0 + 8 < M)
                *reinterpret_cast<__half2*>(&g_h1h[(long long)(row0 + 8) * NHID + col]) =
                    __floats2half2_rn(acc[mt][nt][2], acc[mt][nt][3]);
        }
    }
}

// ---------------- agg1: g1 = relu(Ahat @ h1 + b1), warp per node, fp16 gather
__global__ void __launch_bounds__(256) k_agg1(const float* __restrict__ b1, int n) {
    int gtid = blockIdx.x * blockDim.x + threadIdx.x;
    int node = gtid >> 5;
    int lane = threadIdx.x & 31;
    if (node >= n) return;
    const uint2* h1v = reinterpret_cast<const uint2*>(g_h1h); // 8B = 4 halves per lane
    float dv = g_dinv[node];
    float sw = dv * dv;

    uint2 hu = h1v[(long long)node * 32 + lane];
    float2 p0 = __half22float2(*reinterpret_cast<__half2*>(&hu.x));
    float2 p1 = __half22float2(*reinterpret_cast<__half2*>(&hu.y));
    float ax = p0.x * sw, ay = p0.y * sw, az = p1.x * sw, aw = p1.y * sw;

    int p = g_off[node], end = g_off[node + 1];
    for (; p + 3 < end; p += 4) {
        int2 e0 = g_edge[p],     e1 = g_edge[p + 1];
        int2 e2 = g_edge[p + 2], e3 = g_edge[p + 3];
        float w0 = __int_as_float(e0.y), w1 = __int_as_float(e1.y);
        float w2 = __int_as_float(e2.y), w3 = __int_as_float(e3.y);
        uint2 u0 = h1v[(long long)e0.x * 32 + lane];
        uint2 u1 = h1v[(long long)e1.x * 32 + lane];
        uint2 u2 = h1v[(long long)e2.x * 32 + lane];
        uint2 u3 = h1v[(long long)e3.x * 32 + lane];
        float2 a0 = __half22float2(*reinterpret_cast<__half2*>(&u0.x));
        float2 b0 = __half22float2(*reinterpret_cast<__half2*>(&u0.y));
        float2 a1 = __half22float2(*reinterpret_cast<__half2*>(&u1.x));
        float2 b1v = __half22float2(*reinterpret_cast<__half2*>(&u1.y));
        float2 a2 = __half22float2(*reinterpret_cast<__half2*>(&u2.x));
        float2 b2v = __half22float2(*reinterpret_cast<__half2*>(&u2.y));
        float2 a3 = __half22float2(*reinterpret_cast<__half2*>(&u3.x));
        float2 b3v = __half22float2(*reinterpret_cast<__half2*>(&u3.y));
        ax += a0.x * w0 + a1.x * w1 + a2.x * w2 + a3.x * w3;
        ay += a0.y * w0 + a1.y * w1 + a2.y * w2 + a3.y * w3;
        az += b0.x * w0 + b1v.x * w1 + b2v.x * w2 + b3v.x * w3;
        aw += b0.y * w0 + b1v.y * w1 + b2v.y * w2 + b3v.y * w3;
    }
    for (; p < end; p++) {
        int2 e0 = g_edge[p];
        float w0 = __int_as_float(e0.y);
        uint2 u0 = h1v[(long long)e0.x * 32 + lane];
        float2 a0 = __half22float2(*reinterpret_cast<__half2*>(&u0.x));
        float2 b0 = __half22float2(*reinterpret_cast<__half2*>(&u0.y));
        ax += a0.x * w0; ay += a0.y * w0; az += b0.x * w0; aw += b0.y * w0;
    }
    float4 bb = reinterpret_cast<const float4*>(b1)[lane];
    float4 out;
    out.x = fmaxf(ax + bb.x, 0.f);
    out.y = fmaxf(ay + bb.y, 0.f);
    out.z = fmaxf(az + bb.z, 0.f);
    out.w = fmaxf(aw + bb.w, 0.f);
    reinterpret_cast<float4*>(g_g1)[(long long)node * 32 + lane] = out;
}

// ---------------- GEMM2: h2 = g1(Mx128) @ W2(128x16), reg-blocked, fp16 out
#define GP 68    // s_g row pad (floats)
#define WP 132   // s_wt row pad (floats)
__global__ void __launch_bounds__(128) k_gemm2(const float* __restrict__ W2, int M) {
    __shared__ float s_g[128][GP];   // [node][k-chunk 64]
    __shared__ float s_wt[16][WP];   // [col][k 0..127] transposed W2
    const int tid  = threadIdx.x;
    const int ng   = tid >> 2;       // node group 0..31 (4 nodes each)
    const int cg   = tid & 3;        // col group 0..3 (4 cols each)
    const int node0 = blockIdx.x * 128;

    for (int idx = tid; idx < 2048; idx += 128) {
        int k = idx >> 4, j = idx & 15;
        s_wt[j][k] = W2[idx];
    }

    float acc[4][4];
    #pragma unroll
    for (int m = 0; m < 4; m++)
        #pragma unroll
        for (int j = 0; j < 4; j++) acc[m][j] = 0.f;

    #pragma unroll
    for (int kc = 0; kc < 2; kc++) {
        const int k0 = kc * 64;
        __syncthreads();
        #pragma unroll
        for (int i = 0; i < 16; i++) {
            int idx = i * 128 + tid;
            int nd = idx >> 4, kq = idx & 15;
            float4 v = make_float4(0.f, 0.f, 0.f, 0.f);
            if (node0 + nd < M)
                v = *reinterpret_cast<const float4*>(&g_g1[(long long)(node0 + nd) * NHID + k0 + kq * 4]);
            *reinterpret_cast<float4*>(&s_g[nd][kq * 4]) = v;
        }
        __syncthreads();
        #pragma unroll
        for (int kq = 0; kq < 16; kq++) {
            float4 a[4], b[4];
            #pragma unroll
            for (int m = 0; m < 4; m++)
                a[m] = *reinterpret_cast<const float4*>(&s_g[ng * 4 + m][kq * 4]);
            #pragma unroll
            for (int j = 0; j < 4; j++)
                b[j] = *reinterpret_cast<const float4*>(&s_wt[cg * 4 + j][k0 + kq * 4]);
            #pragma unroll
            for (int m = 0; m < 4; m++)
                #pragma unroll
                for (int j = 0; j < 4; j++)
                    acc[m][j] += a[m].x * b[j].x + a[m].y * b[j].y
                               + a[m].z * b[j].z + a[m].w * b[j].w;
        }
    }

    #pragma unroll
    for (int m = 0; m < 4; m++) {
        int nd = node0 + ng * 4 + m;
        if (nd < M) {
            __half2 q0 = __floats2half2_rn(acc[m][0], acc[m][1]);
            __half2 q1 = __floats2half2_rn(acc[m][2], acc[m][3]);
            *reinterpret_cast<__half2*>(&g_h2h[(long long)nd * 16 + cg * 4])     = q0;
            *reinterpret_cast<__half2*>(&g_h2h[(long long)nd * 16 + cg * 4 + 2]) = q1;
        }
    }
}

// ---------------- agg2: out = Ahat @ h2 + b2, 16 threads per node, fp16 ----
__global__ void __launch_bounds__(256) k_agg2(const float* __restrict__ b2,
                                              float* __restrict__ out, int n) {
    int gtid = blockIdx.x * blockDim.x + threadIdx.x;
    int node = gtid >> 4;
    int lane = threadIdx.x & 15;
    if (node >= n) return;
    float dv = g_dinv[node];
    float acc = __half2float(g_h2h[(long long)node * 16 + lane]) * dv * dv;
    int p = g_off[node], end = g_off[node + 1];
    for (; p + 3 < end; p += 4) {
        int2 e0 = g_edge[p],     e1 = g_edge[p + 1];
        int2 e2 = g_edge[p + 2], e3 = g_edge[p + 3];
        acc += __half2float(g_h2h[(long long)e0.x * 16 + lane]) * __int_as_float(e0.y)
             + __half2float(g_h2h[(long long)e1.x * 16 + lane]) * __int_as_float(e1.y)
             + __half2float(g_h2h[(long long)e2.x * 16 + lane]) * __int_as_float(e2.y)
             + __half2float(g_h2h[(long long)e3.x * 16 + lane]) * __int_as_float(e3.y);
    }
    for (; p < end; p++) {
        int2 e0 = g_edge[p];
        acc += __half2float(g_h2h[(long long)e0.x * 16 + lane]) * __int_as_float(e0.y);
    }
    out[(long long)node * 16 + lane] = acc + b2[lane];
}

// ---------------- launch ----------------------------------------------------
extern "C" void kernel_launch(void* const* d_in, const int* in_sizes, int n_in,
                              void* d_out, int out_size) {
    const float* x  = (const float*)d_in[0];
    const void*  ei = d_in[1];
    const float* W1 = (const float*)d_in[2];
    const float* b1 = (const float*)d_in[3];
    const float* W2 = (const float*)d_in[4];
    const float* b2 = (const float*)d_in[5];
    float* out = (float*)d_out;

    int n = in_sizes[0] / NFEAT;
    int E = in_sizes[1] / 2;

    int gN = (n + 255) / 256;
    int gE = (E + 255) / 256;
    int nb = (n + SCANB - 1) / SCANB;

    const bool fork = g_hx.ok;
    cudaStream_t sb = fork ? g_hx.s2 : (cudaStream_t)0;

    // fork: graph-build chain runs concurrently with GEMM1
    if (fork) {
        cudaEventRecord(g_hx.evA, 0);
        cudaStreamWaitEvent(g_hx.s2, g_hx.evA, 0);
    }
    k_init<<<gN, 256, 0, sb>>>((const int*)ei, n, E);
    k_count<<<gE, 256, 0, sb>>>(ei, E);
    k_scan_block<<<nb, SCANB, 0, sb>>>(n);
    k_scan_tops<<<1, 128, 0, sb>>>(nb, n);
    k_scan_add<<<nb, SCANB, 0, sb>>>(n);
    k_scatter<<<gE, 256, 0, sb>>>(ei, E);
    if (fork) cudaEventRecord(g_hx.evB, g_hx.s2);

    k_gemm1<<<(n + 127) / 128, 256>>>(x, W1, n);

    if (fork) cudaStreamWaitEvent(0, g_hx.evB, 0);  // join before agg1

    k_agg1<<<(n * 32 + 255) / 256, 256>>>(b1, n);
    k_gemm2<<<(n + 127) / 128, 128>>>(W2, n);
    k_agg2<<<(n * 16 + 255) / 256, 256>>>(b2, out, n);
}